// round 7
// baseline (speedup 1.0000x reference)
#include <cuda_runtime.h>

#define BB   4
#define NNN  2048
#define CCC  256
#define HHH  8
#define DHH  32
#define WINW 16
#define SCALE 0.17677669529663687f   // 32^-0.5

typedef unsigned long long u64;

__device__ __forceinline__ u64 fma2(u64 a, u64 b, u64 c) {
    u64 d;
    asm("fma.rn.f32x2 %0, %1, %2, %3;" : "=l"(d) : "l"(a), "l"(b), "l"(c));
    return d;
}
__device__ __forceinline__ u64 pack2(float lo, float hi) {
    u64 d;
    asm("mov.b64 %0, {%1, %2};" : "=l"(d) : "f"(lo), "f"(hi));
    return d;
}
__device__ __forceinline__ float pairsum(u64 p) {
    float lo, hi;
    asm("mov.b64 {%0, %1}, %2;" : "=f"(lo), "=f"(hi) : "l"(p));
    return lo + hi;
}

// -------- scratch (device globals; no allocations allowed) --------
__device__ float g_qkv[3LL * BB * HHH * NNN * DHH];   // [3][B][H][N][32]  24 MB
__device__ float g_comb[(long long)BB * NNN * CCC];   // [B][N][C]          8 MB

// ============================================================
// Kernel 1: QKV GEMM.  X[8192,256] @ W[256,768] -> scatter to g_qkv
// ============================================================
__global__ __launch_bounds__(256) void qkv_gemm_kernel(const float* __restrict__ X,
                                                       const float* __restrict__ W) {
    __shared__ float Xs[16 * 68];
    __shared__ float Ws[16 * 64];
    const int t  = threadIdx.x;
    const int tx = t & 15, ty = t >> 4;
    const int m0 = blockIdx.y * 64;
    const int n0 = blockIdx.x * 64;

    float acc[4][4] = {};

    for (int k0 = 0; k0 < CCC; k0 += 16) {
        {
            int kk = t & 15, mloc = t >> 4;
            #pragma unroll
            for (int r = 0; r < 4; r++) {
                int m = mloc + r * 16;
                Xs[kk * 68 + m] = X[(long long)(m0 + m) * CCC + k0 + kk];
            }
        }
        {
            int nn = t & 63, kk = t >> 6;
            #pragma unroll
            for (int r = 0; r < 4; r++)
                Ws[(kk + r * 4) * 64 + nn] = W[(long long)(k0 + kk + r * 4) * 768 + n0 + nn];
        }
        __syncthreads();
        #pragma unroll
        for (int kk = 0; kk < 16; kk++) {
            float4 a = *(const float4*)(Xs + kk * 68 + ty * 4);
            float4 b = *(const float4*)(Ws + kk * 64 + tx * 4);
            acc[0][0] += a.x * b.x; acc[0][1] += a.x * b.y; acc[0][2] += a.x * b.z; acc[0][3] += a.x * b.w;
            acc[1][0] += a.y * b.x; acc[1][1] += a.y * b.y; acc[1][2] += a.y * b.z; acc[1][3] += a.y * b.w;
            acc[2][0] += a.z * b.x; acc[2][1] += a.z * b.y; acc[2][2] += a.z * b.z; acc[2][3] += a.z * b.w;
            acc[3][0] += a.w * b.x; acc[3][1] += a.w * b.y; acc[3][2] += a.w * b.z; acc[3][3] += a.w * b.w;
        }
        __syncthreads();
    }
    #pragma unroll
    for (int ii = 0; ii < 4; ii++) {
        int row = m0 + ty * 4 + ii;
        int b   = row >> 11;
        int n   = row & 2047;
        #pragma unroll
        for (int jj = 0; jj < 4; jj++) {
            int col = n0 + tx * 4 + jj;
            int t3  = col >> 8;
            int rem = col & 255;
            int h   = rem >> 5;
            int d   = rem & 31;
            g_qkv[((((long long)t3 * BB + b) * HHH + h) * NNN + n) * DHH + d] = acc[ii][jj];
        }
    }
}

// ============================================================
// Kernel 2: fused global + local attention per (b,h, 16-row block)
// 512 threads. f32x2 packed math. Local window fused (block == window).
// smem (floats):
//   S[16][2052]            0
//   qs 16 x 34             QS_OFF
//   rinv[16]               RINV_OFF
//   ks/vt/red/vl region    KS_OFF  (512*34)
//   sl[16][17]             SL_OFF
//   olocal[16][33]         OL_OFF
// ============================================================
#define SS        2052
#define QS_OFF    (16 * SS)                  // 32832
#define RINV_OFF  (QS_OFF + 16 * 34)         // 33376
#define KS_OFF    (RINV_OFF + 16)            // 33392
#define SL_OFF    (KS_OFF + 512 * 34)        // 50800
#define OL_OFF    (SL_OFF + 16 * 17)         // 51072
#define ATTN_FLOATS (OL_OFF + 16 * 33)       // 51600
#define ATTN_SMEM (ATTN_FLOATS * 4)          // 206400 bytes

__global__ __launch_bounds__(512) void attn_global_kernel(float* __restrict__ out_w) {
    extern __shared__ float sm[];
    float* S    = sm;
    float* qs   = sm + QS_OFF;
    float* rinv = sm + RINV_OFF;
    float* ks   = sm + KS_OFF;     // ks[c][d], stride 34
    float* vt   = sm + KS_OFF;     // alias
    float* red  = sm + KS_OFF;     // alias (red[kg][514])
    float* vl   = sm + KS_OFF;     // alias (local V window 16x33)
    float* sl   = sm + SL_OFF;     // local probs 16x17
    float* ol   = sm + OL_OFF;     // local output 16x33

    const int t  = threadIdx.x;
    const int bh = blockIdx.y;
    const int i0 = blockIdx.x * 16;
    const float* Q = g_qkv + (long long)bh * NNN * DHH;
    const float* K = g_qkv + ((long long)BB * HHH + bh) * NNN * DHH;
    const float* V = g_qkv + ((long long)2 * BB * HHH + bh) * NNN * DHH;

    // ---- packed q (pairs over d, scale folded) ----
    if (t < 256) {
        int r = t >> 4, d2 = t & 15;
        float2 qv = *(const float2*)(Q + (long long)(i0 + r) * DHH + 2 * d2);
        *(float2*)(qs + r * 34 + 2 * d2) = make_float2(qv.x * SCALE, qv.y * SCALE);
    }

    // ---------- Phase 1: S = q.K^T  (tiles of 512 cols) ----------
    {
        const int cg = t & 127, rg = t >> 7;   // 4 cols x 4 rows per thread
        for (int kj0 = 0; kj0 < NNN; kj0 += 512) {
            __syncthreads();
            #pragma unroll
            for (int r = 0; r < 8; r++) {
                int idx = t + r * 512;
                int c = idx >> 3, f4 = idx & 7;
                float4 k4 = *(const float4*)(K + (long long)(kj0 + c) * DHH + f4 * 4);
                *(float2*)(ks + c * 34 + f4 * 4)     = make_float2(k4.x, k4.y);
                *(float2*)(ks + c * 34 + f4 * 4 + 2) = make_float2(k4.z, k4.w);
            }
            __syncthreads();

            u64 acc2[4][4] = {};
            #pragma unroll
            for (int d2 = 0; d2 < 16; d2++) {
                u64 q2[4];
                #pragma unroll
                for (int r = 0; r < 4; r++)
                    q2[r] = *(const u64*)(qs + (rg * 4 + r) * 34 + 2 * d2);   // broadcast
                u64 k2[4];
                #pragma unroll
                for (int cc = 0; cc < 4; cc++)
                    k2[cc] = *(const u64*)(ks + (cg + 128 * cc) * 34 + 2 * d2);
                #pragma unroll
                for (int r = 0; r < 4; r++)
                    #pragma unroll
                    for (int cc = 0; cc < 4; cc++)
                        acc2[r][cc] = fma2(q2[r], k2[cc], acc2[r][cc]);
            }
            #pragma unroll
            for (int r = 0; r < 4; r++)
                #pragma unroll
                for (int cc = 0; cc < 4; cc++)
                    S[(rg * 4 + r) * SS + kj0 + cg + 128 * cc] = pairsum(acc2[r][cc]);
        }
    }
    __syncthreads();

    // ---------- Local window attention (block == window), uses raw S ----------
    {
        // V window -> vl[16][33]
        {
            int i = t >> 5, d = t & 31;
            vl[i * 33 + d] = V[(long long)(i0 + i) * DHH + d];
        }
        if (t < 256) {
            int row = t >> 4, j = t & 15;
            float s = S[row * SS + i0 + j];
            float m = s;
            #pragma unroll
            for (int o = 8; o; o >>= 1) m = fmaxf(m, __shfl_xor_sync(0xffffffffu, m, o, 16));
            float e = __expf(s - m);
            float ssum = e;
            #pragma unroll
            for (int o = 8; o; o >>= 1) ssum += __shfl_xor_sync(0xffffffffu, ssum, o, 16);
            sl[row * 17 + j] = e / ssum;
        }
        __syncthreads();
        {
            int row = t >> 5, d = t & 31;
            float a = 0.f;
            #pragma unroll
            for (int j = 0; j < 16; j++) a += sl[row * 17 + j] * vl[j * 33 + d];
            ol[row * 33 + d] = a;
        }
    }
    __syncthreads();

    // ---------- Phase 2: softmax (one warp per row); S := e (unnormalized) ----------
    {
        int row = t >> 5, lane = t & 31;
        float* Sr = S + row * SS;
        float m = -1e30f;
        #pragma unroll
        for (int i = 0; i < 16; i++) {
            float4 v = *(const float4*)(Sr + i * 128 + lane * 4);
            m = fmaxf(m, fmaxf(fmaxf(v.x, v.y), fmaxf(v.z, v.w)));
        }
        #pragma unroll
        for (int o = 16; o; o >>= 1) m = fmaxf(m, __shfl_xor_sync(0xffffffffu, m, o));
        float ssum = 0.f;
        #pragma unroll
        for (int i = 0; i < 16; i++) {
            float4 v = *(float4*)(Sr + i * 128 + lane * 4);
            v.x = __expf(v.x - m); v.y = __expf(v.y - m);
            v.z = __expf(v.z - m); v.w = __expf(v.w - m);
            *(float4*)(Sr + i * 128 + lane * 4) = v;
            ssum += (v.x + v.y) + (v.z + v.w);
        }
        #pragma unroll
        for (int o = 16; o; o >>= 1) ssum += __shfl_xor_sync(0xffffffffu, ssum, o);
        if (lane == 0) rinv[row] = 1.0f / ssum;
    }
    __syncthreads();

    // ---------- Phase 2b: write normalized weights to gmem (float4) ----------
    {
        float* wbase = out_w + (long long)bh * NNN * NNN + (long long)i0 * NNN;
        #pragma unroll 4
        for (int i = 0; i < 16; i++) {
            float inv = rinv[i];
            float4 v = *(const float4*)(S + i * SS + t * 4);
            v.x *= inv; v.y *= inv; v.z *= inv; v.w *= inv;
            *(float4*)(wbase + (long long)i * NNN + t * 4) = v;
        }
    }

    // ---------- Phase 3: O = e.V  (16-way split-k, f32x2 over dims) ----------
    {
        const int kg  = t & 15;          // split-k group
        const int d2g = (t >> 4) & 7;    // 4 dims (2 pairs)
        const int rg  = t >> 7;          // 4 groups of 4 rows
        u64 acc2[4][2] = {};

        for (int vj0 = 0; vj0 < NNN; vj0 += 256) {
            __syncthreads();
            #pragma unroll
            for (int r = 0; r < 4; r++) {
                int idx = t + r * 512;
                int c = idx >> 3, f4 = idx & 7;
                float4 v4 = *(const float4*)(V + (long long)(vj0 + c) * DHH + f4 * 4);
                *(float2*)(vt + c * 34 + f4 * 4)     = make_float2(v4.x, v4.y);
                *(float2*)(vt + c * 34 + f4 * 4 + 2) = make_float2(v4.z, v4.w);
            }
            __syncthreads();

            #pragma unroll 4
            for (int i = 0; i < 16; i++) {
                int kl = i * 16 + kg;
                u64 v2a = *(const u64*)(vt + kl * 34 + d2g * 4);
                u64 v2b = *(const u64*)(vt + kl * 34 + d2g * 4 + 2);
                #pragma unroll
                for (int rr = 0; rr < 4; rr++) {
                    float s = S[(rg * 4 + rr) * SS + vj0 + kl];
                    u64 sp = pack2(s, s);
                    acc2[rr][0] = fma2(sp, v2a, acc2[rr][0]);
                    acc2[rr][1] = fma2(sp, v2b, acc2[rr][1]);
                }
            }
        }
        __syncthreads();   // vt dead; region becomes red[]
        #pragma unroll
        for (int rr = 0; rr < 4; rr++) {
            *(u64*)(red + kg * 514 + (rg * 4 + rr) * 32 + d2g * 4)     = acc2[rr][0];
            *(u64*)(red + kg * 514 + (rg * 4 + rr) * 32 + d2g * 4 + 2) = acc2[rr][1];
        }
        __syncthreads();

        const int b = bh >> 3, h = bh & 7;
        {
            int row = t >> 5, d = t & 31;
            float sum = 0.f;
            #pragma unroll
            for (int k2 = 0; k2 < 16; k2++) sum += red[k2 * 514 + row * 32 + d];
            sum = sum * rinv[row] + ol[row * 33 + d];
            g_comb[((long long)b * NNN + i0 + row) * CCC + h * DHH + d] = sum;
        }
    }
}

// ============================================================
// Kernel 4: output projection.  g_comb[8192,256] @ Wp[256,256] + b -> out
// ============================================================
__global__ __launch_bounds__(256) void proj_gemm_kernel(const float* __restrict__ W,
                                                        const float* __restrict__ bias,
                                                        float* __restrict__ out) {
    __shared__ float Xs[16 * 68];
    __shared__ float Ws[16 * 64];
    const int t  = threadIdx.x;
    const int tx = t & 15, ty = t >> 4;
    const int m0 = blockIdx.y * 64;
    const int n0 = blockIdx.x * 64;

    float acc[4][4] = {};
    for (int k0 = 0; k0 < CCC; k0 += 16) {
        {
            int kk = t & 15, mloc = t >> 4;
            #pragma unroll
            for (int r = 0; r < 4; r++) {
                int m = mloc + r * 16;
                Xs[kk * 68 + m] = g_comb[(long long)(m0 + m) * CCC + k0 + kk];
            }
        }
        {
            int nn = t & 63, kk = t >> 6;
            #pragma unroll
            for (int r = 0; r < 4; r++)
                Ws[(kk + r * 4) * 64 + nn] = W[(long long)(k0 + kk + r * 4) * CCC + n0 + nn];
        }
        __syncthreads();
        #pragma unroll
        for (int kk = 0; kk < 16; kk++) {
            float4 a = *(const float4*)(Xs + kk * 68 + ty * 4);
            float4 b = *(const float4*)(Ws + kk * 64 + tx * 4);
            acc[0][0] += a.x * b.x; acc[0][1] += a.x * b.y; acc[0][2] += a.x * b.z; acc[0][3] += a.x * b.w;
            acc[1][0] += a.y * b.x; acc[1][1] += a.y * b.y; acc[1][2] += a.y * b.z; acc[1][3] += a.y * b.w;
            acc[2][0] += a.z * b.x; acc[2][1] += a.z * b.y; acc[2][2] += a.z * b.z; acc[2][3] += a.z * b.w;
            acc[3][0] += a.w * b.x; acc[3][1] += a.w * b.y; acc[3][2] += a.w * b.z; acc[3][3] += a.w * b.w;
        }
        __syncthreads();
    }
    #pragma unroll
    for (int ii = 0; ii < 4; ii++) {
        int row = m0 + ty * 4 + ii;
        #pragma unroll
        for (int jj = 0; jj < 4; jj++) {
            int col = n0 + tx * 4 + jj;
            out[(long long)row * CCC + col] = acc[ii][jj] + bias[col];
        }
    }
}

// ============================================================
extern "C" void kernel_launch(void* const* d_in, const int* in_sizes, int n_in,
                              void* d_out, int out_size) {
    const float* x     = (const float*)d_in[0];
    const float* Wqkv  = (const float*)d_in[1];
    const float* Wproj = (const float*)d_in[2];
    const float* bproj = (const float*)d_in[3];
    float* out   = (float*)d_out;
    float* out_w = out + (long long)BB * NNN * CCC;

    cudaFuncSetAttribute(attn_global_kernel,
                         cudaFuncAttributeMaxDynamicSharedMemorySize, ATTN_SMEM);

    qkv_gemm_kernel<<<dim3(12, 128), 256>>>(x, Wqkv);
    attn_global_kernel<<<dim3(NNN / 16, BB * HHH), 512, ATTN_SMEM>>>(out_w);
    proj_gemm_kernel<<<dim3(CCC / 64, (BB * NNN) / 64), 256>>>(Wproj, bproj, out);
}

// round 9
// speedup vs baseline: 1.0978x; 1.0978x over previous
#include <cuda_runtime.h>

#define BB   4
#define NNN  2048
#define CCC  256
#define HHH  8
#define DHH  32
#define WINW 16
#define SCALE 0.17677669529663687f   // 32^-0.5

typedef unsigned long long u64;

__device__ __forceinline__ u64 fma2(u64 a, u64 b, u64 c) {
    u64 d;
    asm("fma.rn.f32x2 %0, %1, %2, %3;" : "=l"(d) : "l"(a), "l"(b), "l"(c));
    return d;
}
__device__ __forceinline__ u64 pack2(float lo, float hi) {
    u64 d;
    asm("mov.b64 %0, {%1, %2};" : "=l"(d) : "f"(lo), "f"(hi));
    return d;
}
__device__ __forceinline__ float pairsum(u64 p) {
    float lo, hi;
    asm("mov.b64 {%0, %1}, %2;" : "=f"(lo), "=f"(hi) : "l"(p));
    return lo + hi;
}
__device__ __forceinline__ void unpack2(u64 p, float& lo, float& hi) {
    asm("mov.b64 {%0, %1}, %2;" : "=f"(lo), "=f"(hi) : "l"(p));
}

// -------- scratch (device globals; no allocations allowed) --------
__device__ float g_qkv[3LL * BB * HHH * NNN * DHH];   // [3][B][H][N][32]
__device__ float g_comb[(long long)BB * NNN * CCC];   // [B][N][C]

// ============================================================
// Kernel 1: QKV GEMM.  X[8192,256] @ W[256,768] -> scatter to g_qkv
// 128x128 tile, 256 threads, 8x8 microtile, f32x2 over cols
// ============================================================
__global__ __launch_bounds__(256) void qkv_gemm_kernel(const float* __restrict__ X,
                                                       const float* __restrict__ W) {
    __shared__ float Xs[16 * 132];   // Xs[k][m]
    __shared__ float Ws[16 * 128];   // Ws[k][n]
    const int t  = threadIdx.x;
    const int tx = t & 15, ty = t >> 4;
    const int m0 = blockIdx.y * 128;
    const int n0 = blockIdx.x * 128;

    u64 acc2[8][4] = {};

    for (int k0 = 0; k0 < CCC; k0 += 16) {
        #pragma unroll
        for (int r = 0; r < 2; r++) {
            int idx = t + r * 256;
            int m = idx >> 2, c = idx & 3;
            float4 x4 = *(const float4*)(X + (long long)(m0 + m) * CCC + k0 + c * 4);
            Xs[(4 * c + 0) * 132 + m] = x4.x;
            Xs[(4 * c + 1) * 132 + m] = x4.y;
            Xs[(4 * c + 2) * 132 + m] = x4.z;
            Xs[(4 * c + 3) * 132 + m] = x4.w;
        }
        #pragma unroll
        for (int r = 0; r < 2; r++) {
            int idx = t + r * 256;
            int k = idx >> 5, nq = idx & 31;
            *(float4*)(Ws + k * 128 + nq * 4) =
                *(const float4*)(W + (long long)(k0 + k) * 768 + n0 + nq * 4);
        }
        __syncthreads();
        #pragma unroll
        for (int kk = 0; kk < 16; kk++) {
            float4 aa = *(const float4*)(Xs + kk * 132 + ty * 8);
            float4 ab = *(const float4*)(Xs + kk * 132 + ty * 8 + 4);
            u64 bp[4];
            #pragma unroll
            for (int c = 0; c < 4; c++)
                bp[c] = *(const u64*)(Ws + kk * 128 + tx * 8 + 2 * c);
            float av[8] = {aa.x, aa.y, aa.z, aa.w, ab.x, ab.y, ab.z, ab.w};
            #pragma unroll
            for (int r = 0; r < 8; r++) {
                u64 ap = pack2(av[r], av[r]);
                #pragma unroll
                for (int c = 0; c < 4; c++)
                    acc2[r][c] = fma2(ap, bp[c], acc2[r][c]);
            }
        }
        __syncthreads();
    }
    #pragma unroll
    for (int r = 0; r < 8; r++) {
        int row = m0 + ty * 8 + r;
        int b   = row >> 11;
        int n   = row & 2047;
        #pragma unroll
        for (int c = 0; c < 4; c++) {
            float lo, hi;
            unpack2(acc2[r][c], lo, hi);
            int col = n0 + tx * 8 + 2 * c;
            #pragma unroll
            for (int j = 0; j < 2; j++) {
                int cc  = col + j;
                int t3  = cc >> 8;
                int rem = cc & 255;
                int h   = rem >> 5;
                int d   = rem & 31;
                g_qkv[((((long long)t3 * BB + b) * HHH + h) * NNN + n) * DHH + d] =
                    (j == 0) ? lo : hi;
            }
        }
    }
}

// ============================================================
// Kernel 2: fused global + local attention per (b,h, 16-row block)
// 256 threads. f32x2. Crossbar-optimal microtiles.
// ============================================================
#define SS        2052
#define QS_OFF    (16 * SS)                  // 32832
#define RINV_OFF  (QS_OFF + 16 * 34)         // 33376
#define KS_OFF    (RINV_OFF + 16)            // 33392
#define SL_OFF    (KS_OFF + 512 * 34)        // 50800
#define OL_OFF    (SL_OFF + 16 * 17)         // 51072
#define ATTN_FLOATS (OL_OFF + 16 * 33)       // 51600
#define ATTN_SMEM (ATTN_FLOATS * 4)          // 206400 bytes

__global__ __launch_bounds__(256) void attn_global_kernel(float* __restrict__ out_w) {
    extern __shared__ float sm[];
    float* S    = sm;
    float* qs   = sm + QS_OFF;     // qs[i] stride 34 (pairs over d, scale folded)
    float* rinv = sm + RINV_OFF;
    float* ks   = sm + KS_OFF;     // ks[c][d], stride 34
    float* vt   = sm + KS_OFF;     // alias
    float* red  = sm + KS_OFF;     // alias  red[kg][514], kg<32
    float* vl   = sm + KS_OFF;     // alias  local V window 16x33
    float* sl   = sm + SL_OFF;
    float* ol   = sm + OL_OFF;

    const int t  = threadIdx.x;
    const int bh = blockIdx.y;
    const int i0 = blockIdx.x * 16;
    const float* Q = g_qkv + (long long)bh * NNN * DHH;
    const float* K = g_qkv + ((long long)BB * HHH + bh) * NNN * DHH;
    const float* V = g_qkv + ((long long)2 * BB * HHH + bh) * NNN * DHH;

    // ---- packed q (pairs over d, scale folded) ----
    {
        int r = t >> 4, d2 = t & 15;
        float2 qv = *(const float2*)(Q + (long long)(i0 + r) * DHH + 2 * d2);
        *(float2*)(qs + r * 34 + 2 * d2) = make_float2(qv.x * SCALE, qv.y * SCALE);
    }

    // ---------- Phase 1: S = q.K^T  (8 rows x 4 cols / thread) ----------
    {
        const int cg = t & 127, rg = t >> 7;   // 128 col-groups, 2 row-groups
        for (int kj0 = 0; kj0 < NNN; kj0 += 512) {
            __syncthreads();
            #pragma unroll
            for (int r = 0; r < 16; r++) {
                int idx = t + r * 256;
                int c = idx >> 3, f4 = idx & 7;
                float4 k4 = *(const float4*)(K + (long long)(kj0 + c) * DHH + f4 * 4);
                *(float2*)(ks + c * 34 + f4 * 4)     = make_float2(k4.x, k4.y);
                *(float2*)(ks + c * 34 + f4 * 4 + 2) = make_float2(k4.z, k4.w);
            }
            __syncthreads();

            u64 acc2[8][4] = {};
            #pragma unroll
            for (int d2 = 0; d2 < 16; d2++) {
                u64 k2[4];
                #pragma unroll
                for (int cc = 0; cc < 4; cc++)
                    k2[cc] = *(const u64*)(ks + (cg + 128 * cc) * 34 + 2 * d2);
                #pragma unroll
                for (int r = 0; r < 8; r++) {
                    u64 q2 = *(const u64*)(qs + (rg * 8 + r) * 34 + 2 * d2);  // bcast
                    #pragma unroll
                    for (int cc = 0; cc < 4; cc++)
                        acc2[r][cc] = fma2(q2, k2[cc], acc2[r][cc]);
                }
            }
            #pragma unroll
            for (int r = 0; r < 8; r++)
                #pragma unroll
                for (int cc = 0; cc < 4; cc++)
                    S[(rg * 8 + r) * SS + kj0 + cg + 128 * cc] = pairsum(acc2[r][cc]);
        }
    }
    __syncthreads();

    // ---------- Local window attention (block == window), raw S subtile ----------
    {
        #pragma unroll
        for (int r = 0; r < 2; r++) {
            int idx = t + r * 256;
            int i = idx >> 5, d = idx & 31;
            vl[i * 33 + d] = V[(long long)(i0 + i) * DHH + d];
        }
        {
            int row = t >> 4, j = t & 15;
            float s = S[row * SS + i0 + j];
            float m = s;
            #pragma unroll
            for (int o = 8; o; o >>= 1) m = fmaxf(m, __shfl_xor_sync(0xffffffffu, m, o, 16));
            float e = __expf(s - m);
            float ssum = e;
            #pragma unroll
            for (int o = 8; o; o >>= 1) ssum += __shfl_xor_sync(0xffffffffu, ssum, o, 16);
            sl[row * 17 + j] = e / ssum;
        }
        __syncthreads();
        #pragma unroll
        for (int r = 0; r < 2; r++) {
            int idx = t + r * 256;
            int row = idx >> 5, d = idx & 31;
            float a = 0.f;
            #pragma unroll
            for (int j = 0; j < 16; j++) a += sl[row * 17 + j] * vl[j * 33 + d];
            ol[row * 33 + d] = a;
        }
    }
    __syncthreads();

    // ---------- Phase 2: softmax stats (16 lanes/row); S := e ----------
    {
        int row = t >> 4, lane = t & 15;
        float* Sr = S + row * SS;
        float m = -1e30f;
        #pragma unroll 8
        for (int i = 0; i < 32; i++) {
            float4 v = *(const float4*)(Sr + i * 64 + lane * 4);
            m = fmaxf(m, fmaxf(fmaxf(v.x, v.y), fmaxf(v.z, v.w)));
        }
        #pragma unroll
        for (int o = 8; o; o >>= 1) m = fmaxf(m, __shfl_xor_sync(0xffffffffu, m, o, 16));
        float ssum = 0.f;
        #pragma unroll 8
        for (int i = 0; i < 32; i++) {
            float4 v = *(float4*)(Sr + i * 64 + lane * 4);
            v.x = __expf(v.x - m); v.y = __expf(v.y - m);
            v.z = __expf(v.z - m); v.w = __expf(v.w - m);
            *(float4*)(Sr + i * 64 + lane * 4) = v;
            ssum += (v.x + v.y) + (v.z + v.w);
        }
        #pragma unroll
        for (int o = 8; o; o >>= 1) ssum += __shfl_xor_sync(0xffffffffu, ssum, o, 16);
        if (lane == 0) rinv[row] = 1.0f / ssum;
    }
    __syncthreads();

    // ---------- Phase 3: weights write (interleaved) + O = e.V ----------
    {
        const int kg = t & 31;           // split-k 32
        const int dg = (t >> 5) & 3;     // 8 dims (4 pairs)
        const int rg = t >> 7;           // 2 groups of 8 rows
        u64 acc2[8][4] = {};
        float* wbase = out_w + (long long)bh * NNN * NNN + (long long)i0 * NNN;

        for (int vj0 = 0; vj0 < NNN; vj0 += 256) {
            __syncthreads();
            #pragma unroll
            for (int r = 0; r < 8; r++) {
                int idx = t + r * 256;
                int c = idx >> 3, f4 = idx & 7;
                float4 v4 = *(const float4*)(V + (long long)(vj0 + c) * DHH + f4 * 4);
                *(float2*)(vt + c * 34 + f4 * 4)     = make_float2(v4.x, v4.y);
                *(float2*)(vt + c * 34 + f4 * 4 + 2) = make_float2(v4.z, v4.w);
            }
            __syncthreads();

            // write normalized weights for this column chunk (drains during FFMA)
            #pragma unroll
            for (int s2 = 0; s2 < 4; s2++) {
                int idx = t + s2 * 256;
                int row = idx >> 6, colq = idx & 63;
                float inv = rinv[row];
                float4 v = *(const float4*)(S + row * SS + vj0 + colq * 4);
                v.x *= inv; v.y *= inv; v.z *= inv; v.w *= inv;
                *(float4*)(wbase + (long long)row * NNN + vj0 + colq * 4) = v;
            }

            #pragma unroll
            for (int i = 0; i < 8; i++) {
                int kl = i * 32 + kg;
                u64 v2[4];
                #pragma unroll
                for (int c = 0; c < 4; c++)
                    v2[c] = *(const u64*)(vt + kl * 34 + dg * 8 + 2 * c);
                #pragma unroll
                for (int rr = 0; rr < 8; rr++) {
                    float s = S[(rg * 8 + rr) * SS + vj0 + kl];
                    u64 sp = pack2(s, s);
                    #pragma unroll
                    for (int c = 0; c < 4; c++)
                        acc2[rr][c] = fma2(sp, v2[c], acc2[rr][c]);
                }
            }
        }
        __syncthreads();   // vt dead; region becomes red[]
        #pragma unroll
        for (int rr = 0; rr < 8; rr++)
            #pragma unroll
            for (int c = 0; c < 4; c++)
                *(u64*)(red + kg * 514 + (rg * 8 + rr) * 32 + dg * 8 + 2 * c) = acc2[rr][c];
        __syncthreads();

        const int b = bh >> 3, h = bh & 7;
        #pragma unroll
        for (int s2 = 0; s2 < 2; s2++) {
            int out = t + s2 * 256;
            int row = out >> 5, d = out & 31;
            float sum = 0.f;
            #pragma unroll
            for (int k2 = 0; k2 < 32; k2++) sum += red[k2 * 514 + row * 32 + d];
            sum = sum * rinv[row] + ol[row * 33 + d];
            g_comb[((long long)b * NNN + i0 + row) * CCC + h * DHH + d] = sum;
        }
    }
}

// ============================================================
// Kernel 4: output projection. 128x128 tile, f32x2.
// ============================================================
__global__ __launch_bounds__(256) void proj_gemm_kernel(const float* __restrict__ W,
                                                        const float* __restrict__ bias,
                                                        float* __restrict__ out) {
    __shared__ float Xs[16 * 132];
    __shared__ float Ws[16 * 128];
    const int t  = threadIdx.x;
    const int tx = t & 15, ty = t >> 4;
    const int m0 = blockIdx.y * 128;
    const int n0 = blockIdx.x * 128;

    u64 acc2[8][4] = {};

    for (int k0 = 0; k0 < CCC; k0 += 16) {
        #pragma unroll
        for (int r = 0; r < 2; r++) {
            int idx = t + r * 256;
            int m = idx >> 2, c = idx & 3;
            float4 x4 = *(const float4*)(g_comb + (long long)(m0 + m) * CCC + k0 + c * 4);
            Xs[(4 * c + 0) * 132 + m] = x4.x;
            Xs[(4 * c + 1) * 132 + m] = x4.y;
            Xs[(4 * c + 2) * 132 + m] = x4.z;
            Xs[(4 * c + 3) * 132 + m] = x4.w;
        }
        #pragma unroll
        for (int r = 0; r < 2; r++) {
            int idx = t + r * 256;
            int k = idx >> 5, nq = idx & 31;
            *(float4*)(Ws + k * 128 + nq * 4) =
                *(const float4*)(W + (long long)(k0 + k) * CCC + n0 + nq * 4);
        }
        __syncthreads();
        #pragma unroll
        for (int kk = 0; kk < 16; kk++) {
            float4 aa = *(const float4*)(Xs + kk * 132 + ty * 8);
            float4 ab = *(const float4*)(Xs + kk * 132 + ty * 8 + 4);
            u64 bp[4];
            #pragma unroll
            for (int c = 0; c < 4; c++)
                bp[c] = *(const u64*)(Ws + kk * 128 + tx * 8 + 2 * c);
            float av[8] = {aa.x, aa.y, aa.z, aa.w, ab.x, ab.y, ab.z, ab.w};
            #pragma unroll
            for (int r = 0; r < 8; r++) {
                u64 ap = pack2(av[r], av[r]);
                #pragma unroll
                for (int c = 0; c < 4; c++)
                    acc2[r][c] = fma2(ap, bp[c], acc2[r][c]);
            }
        }
        __syncthreads();
    }
    #pragma unroll
    for (int r = 0; r < 8; r++) {
        int row = m0 + ty * 8 + r;
        #pragma unroll
        for (int c = 0; c < 4; c++) {
            int col = n0 + tx * 8 + 2 * c;
            float lo, hi;
            unpack2(acc2[r][c], lo, hi);
            *(float2*)(out + (long long)row * CCC + col) =
                make_float2(lo + bias[col], hi + bias[col + 1]);
        }
    }
}

// ============================================================
extern "C" void kernel_launch(void* const* d_in, const int* in_sizes, int n_in,
                              void* d_out, int out_size) {
    const float* x     = (const float*)d_in[0];
    const float* Wqkv  = (const float*)d_in[1];
    const float* Wproj = (const float*)d_in[2];
    const float* bproj = (const float*)d_in[3];
    float* out   = (float*)d_out;
    float* out_w = out + (long long)BB * NNN * CCC;

    cudaFuncSetAttribute(attn_global_kernel,
                         cudaFuncAttributeMaxDynamicSharedMemorySize, ATTN_SMEM);

    qkv_gemm_kernel<<<dim3(6, 64), 256>>>(x, Wqkv);
    attn_global_kernel<<<dim3(NNN / 16, BB * HHH), 256, ATTN_SMEM>>>(out_w);
    proj_gemm_kernel<<<dim3(2, 64), 256>>>(Wproj, bproj, out);
}

// round 10
// speedup vs baseline: 1.1732x; 1.0687x over previous
#include <cuda_runtime.h>

#define BB   4
#define NNN  2048
#define CCC  256
#define HHH  8
#define DHH  32
#define WINW 16
#define SCALE 0.17677669529663687f   // 32^-0.5

typedef unsigned long long u64;

__device__ __forceinline__ u64 fma2(u64 a, u64 b, u64 c) {
    u64 d;
    asm("fma.rn.f32x2 %0, %1, %2, %3;" : "=l"(d) : "l"(a), "l"(b), "l"(c));
    return d;
}
__device__ __forceinline__ u64 pack2(float lo, float hi) {
    u64 d;
    asm("mov.b64 %0, {%1, %2};" : "=l"(d) : "f"(lo), "f"(hi));
    return d;
}
__device__ __forceinline__ float pairsum(u64 p) {
    float lo, hi;
    asm("mov.b64 {%0, %1}, %2;" : "=f"(lo), "=f"(hi) : "l"(p));
    return lo + hi;
}
__device__ __forceinline__ void unpack2(u64 p, float& lo, float& hi) {
    asm("mov.b64 {%0, %1}, %2;" : "=f"(lo), "=f"(hi) : "l"(p));
}

// -------- scratch (device globals; no allocations allowed) --------
__device__ float g_qkv[3LL * BB * HHH * NNN * DHH];   // [3][B][H][N][32]
__device__ float g_comb[(long long)BB * NNN * CCC];   // [B][N][C]

// ============================================================
// Kernel 1: QKV GEMM.  X[8192,256] @ W[256,768] -> scatter to g_qkv
// 128x128 tile, 256 threads, 8x8 microtile (cols strided 2tx+32c),
// double-buffered k-tiles with register prefetch.
// ============================================================
__global__ __launch_bounds__(256) void qkv_gemm_kernel(const float* __restrict__ X,
                                                       const float* __restrict__ W) {
    __shared__ float Xs[2][16 * 132];   // Xs[k][m]
    __shared__ float Ws[2][16 * 128];   // Ws[k][n]
    const int t  = threadIdx.x;
    const int tx = t & 15, ty = t >> 4;
    const int m0 = blockIdx.y * 128;
    const int n0 = blockIdx.x * 128;

    u64 acc2[8][4] = {};
    float4 px[2], pw[2];

    const int lm = t >> 2, lc = t & 3;          // X loader coords
    const int lk = t >> 5, lnq = t & 31;        // W loader coords

#define QKV_LDG(K0) {                                                              \
        px[0] = *(const float4*)(X + (long long)(m0 + lm) * CCC + (K0) + 4 * lc);  \
        px[1] = *(const float4*)(X + (long long)(m0 + lm + 64) * CCC + (K0) + 4 * lc); \
        pw[0] = *(const float4*)(W + (long long)((K0) + lk) * 768 + n0 + 4 * lnq); \
        pw[1] = *(const float4*)(W + (long long)((K0) + lk + 8) * 768 + n0 + 4 * lnq); }
#define QKV_STS(BUF) {                                                   \
        float* xp = Xs[BUF]; float* wp = Ws[BUF];                        \
        xp[(4 * lc + 0) * 132 + lm] = px[0].x;                           \
        xp[(4 * lc + 1) * 132 + lm] = px[0].y;                           \
        xp[(4 * lc + 2) * 132 + lm] = px[0].z;                           \
        xp[(4 * lc + 3) * 132 + lm] = px[0].w;                           \
        xp[(4 * lc + 0) * 132 + lm + 64] = px[1].x;                      \
        xp[(4 * lc + 1) * 132 + lm + 64] = px[1].y;                      \
        xp[(4 * lc + 2) * 132 + lm + 64] = px[1].z;                      \
        xp[(4 * lc + 3) * 132 + lm + 64] = px[1].w;                      \
        *(float4*)(wp + lk * 128 + 4 * lnq) = pw[0];                     \
        *(float4*)(wp + (lk + 8) * 128 + 4 * lnq) = pw[1]; }

    QKV_LDG(0); QKV_STS(0); QKV_LDG(16);
    __syncthreads();

    for (int kt = 0; kt < 16; kt++) {
        const float* xp = Xs[kt & 1];
        const float* wp = Ws[kt & 1];
        #pragma unroll
        for (int kk = 0; kk < 16; kk++) {
            float4 aa = *(const float4*)(xp + kk * 132 + ty * 8);
            float4 ab = *(const float4*)(xp + kk * 132 + ty * 8 + 4);
            u64 bp[4];
            #pragma unroll
            for (int c = 0; c < 4; c++)
                bp[c] = *(const u64*)(wp + kk * 128 + tx * 2 + 32 * c);
            float av[8] = {aa.x, aa.y, aa.z, aa.w, ab.x, ab.y, ab.z, ab.w};
            #pragma unroll
            for (int r = 0; r < 8; r++) {
                u64 ap = pack2(av[r], av[r]);
                #pragma unroll
                for (int c = 0; c < 4; c++)
                    acc2[r][c] = fma2(ap, bp[c], acc2[r][c]);
            }
        }
        if (kt < 15) QKV_STS((kt + 1) & 1);
        if (kt < 14) QKV_LDG((kt + 2) * 16);
        __syncthreads();
    }
    #pragma unroll
    for (int r = 0; r < 8; r++) {
        int row = m0 + ty * 8 + r;
        int b   = row >> 11;
        int n   = row & 2047;
        #pragma unroll
        for (int c = 0; c < 4; c++) {
            float lo, hi;
            unpack2(acc2[r][c], lo, hi);
            int col = n0 + tx * 2 + 32 * c;
            #pragma unroll
            for (int j = 0; j < 2; j++) {
                int cc  = col + j;
                int t3  = cc >> 8;
                int rem = cc & 255;
                int h   = rem >> 5;
                int d   = rem & 31;
                g_qkv[((((long long)t3 * BB + b) * HHH + h) * NNN + n) * DHH + d] =
                    (j == 0) ? lo : hi;
            }
        }
    }
}

// ============================================================
// Kernel 2: fused global + local attention per (b,h, 16-row block)
// 256 threads, f32x2, double-buffered 256-col/row tiles, reg prefetch.
// ============================================================
#define SS        2052
#define QS_OFF    (16 * SS)                  // 32832
#define RINV_OFF  (QS_OFF + 16 * 34)         // 33376
#define KB_OFF    (RINV_OFF + 16)            // 33392
#define KTILE     (256 * 34)                 // 8704 floats per buffer
#define SL_OFF    (KB_OFF + 2 * KTILE)       // 50800
#define OL_OFF    (SL_OFF + 16 * 17)         // 51072
#define ATTN_FLOATS (OL_OFF + 16 * 33)       // 51600
#define ATTN_SMEM (ATTN_FLOATS * 4)          // 206400 bytes

__global__ __launch_bounds__(256) void attn_global_kernel(float* __restrict__ out_w) {
    extern __shared__ float sm[];
    float* S    = sm;
    float* qs   = sm + QS_OFF;     // qs[i] stride 34, scale folded
    float* rinv = sm + RINV_OFF;
    float* kb   = sm + KB_OFF;     // double buffer, stride 34
    float* red  = sm + KB_OFF;     // alias: red[kg][514], kg<32 (16448 fl)
    float* vl   = sm + KB_OFF;     // alias: local V window 16x33
    float* sl   = sm + SL_OFF;
    float* ol   = sm + OL_OFF;

    const int t  = threadIdx.x;
    const int bh = blockIdx.y;
    const int i0 = blockIdx.x * 16;
    const float* Q = g_qkv + (long long)bh * NNN * DHH;
    const float* K = g_qkv + ((long long)BB * HHH + bh) * NNN * DHH;
    const float* V = g_qkv + ((long long)2 * BB * HHH + bh) * NNN * DHH;

    const int plc = t >> 3, plf = t & 7;     // tile loader coords (c, f4)
    float4 pk[8];

#define TILE_LDG(SRC, N) { long long base = (long long)(N) * 256 * DHH;         \
        _Pragma("unroll")                                                       \
        for (int r = 0; r < 8; r++)                                             \
            pk[r] = *(const float4*)((SRC) + base + (long long)(plc + r * 32) * DHH + plf * 4); }
#define TILE_STS(BUF) { float* bp = kb + (BUF) * KTILE;                          \
        _Pragma("unroll")                                                        \
        for (int r = 0; r < 8; r++) {                                            \
            float* p = bp + (plc + r * 32) * 34 + plf * 4;                       \
            *(float2*)(p)     = make_float2(pk[r].x, pk[r].y);                   \
            *(float2*)(p + 2) = make_float2(pk[r].z, pk[r].w); } }

    // ---- packed q (pairs over d, scale folded) ----
    {
        int r = t >> 4, d2 = t & 15;
        float2 qv = *(const float2*)(Q + (long long)(i0 + r) * DHH + 2 * d2);
        *(float2*)(qs + r * 34 + 2 * d2) = make_float2(qv.x * SCALE, qv.y * SCALE);
    }

    // ---------- Phase 1: S = q.K^T  (8 tiles of 256 cols, pipelined) ----------
    {
        const int cg = t & 127, rg = t >> 7;   // 8 rows x 2 cols / thread
        TILE_LDG(K, 0); TILE_STS(0); TILE_LDG(K, 1);
        __syncthreads();
        for (int n = 0; n < 8; n++) {
            const float* bp = kb + (n & 1) * KTILE;
            const int kj0 = n * 256;
            u64 acc2[8][2] = {};
            #pragma unroll
            for (int d2 = 0; d2 < 16; d2++) {
                u64 k2a = *(const u64*)(bp + cg * 34 + 2 * d2);
                u64 k2b = *(const u64*)(bp + (cg + 128) * 34 + 2 * d2);
                #pragma unroll
                for (int r = 0; r < 8; r++) {
                    u64 q2 = *(const u64*)(qs + (rg * 8 + r) * 34 + 2 * d2);  // bcast
                    acc2[r][0] = fma2(q2, k2a, acc2[r][0]);
                    acc2[r][1] = fma2(q2, k2b, acc2[r][1]);
                }
            }
            #pragma unroll
            for (int r = 0; r < 8; r++) {
                S[(rg * 8 + r) * SS + kj0 + cg]       = pairsum(acc2[r][0]);
                S[(rg * 8 + r) * SS + kj0 + cg + 128] = pairsum(acc2[r][1]);
            }
            if (n < 7) TILE_STS((n + 1) & 1);
            if (n < 6) TILE_LDG(K, n + 2);
            __syncthreads();
        }
    }

    // ---------- Local window attention (block == window), raw S subtile ----------
    {
        #pragma unroll
        for (int r = 0; r < 2; r++) {
            int idx = t + r * 256;
            int i = idx >> 5, d = idx & 31;
            vl[i * 33 + d] = V[(long long)(i0 + i) * DHH + d];
        }
        {
            int row = t >> 4, j = t & 15;
            float s = S[row * SS + i0 + j];
            float m = s;
            #pragma unroll
            for (int o = 8; o; o >>= 1) m = fmaxf(m, __shfl_xor_sync(0xffffffffu, m, o, 16));
            float e = __expf(s - m);
            float ssum = e;
            #pragma unroll
            for (int o = 8; o; o >>= 1) ssum += __shfl_xor_sync(0xffffffffu, ssum, o, 16);
            sl[row * 17 + j] = e / ssum;
        }
        __syncthreads();
        #pragma unroll
        for (int r = 0; r < 2; r++) {
            int idx = t + r * 256;
            int row = idx >> 5, d = idx & 31;
            float a = 0.f;
            #pragma unroll
            for (int j = 0; j < 16; j++) a += sl[row * 17 + j] * vl[j * 33 + d];
            ol[row * 33 + d] = a;
        }
    }
    __syncthreads();

    // ---------- Phase 2: softmax stats (16 lanes/row); S := e ----------
    {
        int row = t >> 4, lane = t & 15;
        float* Sr = S + row * SS;
        float m = -1e30f;
        #pragma unroll 8
        for (int i = 0; i < 32; i++) {
            float4 v = *(const float4*)(Sr + i * 64 + lane * 4);
            m = fmaxf(m, fmaxf(fmaxf(v.x, v.y), fmaxf(v.z, v.w)));
        }
        #pragma unroll
        for (int o = 8; o; o >>= 1) m = fmaxf(m, __shfl_xor_sync(0xffffffffu, m, o, 16));
        float ssum = 0.f;
        #pragma unroll 8
        for (int i = 0; i < 32; i++) {
            float4 v = *(float4*)(Sr + i * 64 + lane * 4);
            v.x = __expf(v.x - m); v.y = __expf(v.y - m);
            v.z = __expf(v.z - m); v.w = __expf(v.w - m);
            *(float4*)(Sr + i * 64 + lane * 4) = v;
            ssum += (v.x + v.y) + (v.z + v.w);
        }
        #pragma unroll
        for (int o = 8; o; o >>= 1) ssum += __shfl_xor_sync(0xffffffffu, ssum, o, 16);
        if (lane == 0) rinv[row] = 1.0f / ssum;
    }
    __syncthreads();

    // ---------- Phase 3: weights write + O = e.V  (8 tiles of 256 rows) ----------
    {
        const int kg = t & 31;           // split-k 32
        const int dg = (t >> 5) & 3;     // 8 dims (4 pairs)
        const int rg = t >> 7;           // 2 groups of 8 rows
        u64 acc2[8][4] = {};
        float* wbase = out_w + (long long)bh * NNN * NNN + (long long)i0 * NNN;

        TILE_LDG(V, 0); TILE_STS(0); TILE_LDG(V, 1);
        __syncthreads();
        for (int n = 0; n < 8; n++) {
            const float* vb = kb + (n & 1) * KTILE;
            const int vj0 = n * 256;

            #pragma unroll
            for (int i = 0; i < 8; i++) {
                int kl = i * 32 + kg;
                u64 v2[4];
                #pragma unroll
                for (int c = 0; c < 4; c++)
                    v2[c] = *(const u64*)(vb + kl * 34 + dg * 8 + 2 * c);
                #pragma unroll
                for (int rr = 0; rr < 8; rr++) {
                    float s = S[(rg * 8 + rr) * SS + vj0 + kl];
                    u64 sp = pack2(s, s);
                    #pragma unroll
                    for (int c = 0; c < 4; c++)
                        acc2[rr][c] = fma2(sp, v2[c], acc2[rr][c]);
                }
            }

            // write normalized weights for this column chunk (STG drains async)
            #pragma unroll
            for (int s2 = 0; s2 < 4; s2++) {
                int idx = t + s2 * 256;
                int row = idx >> 6, colq = idx & 63;
                float inv = rinv[row];
                float4 v = *(const float4*)(S + row * SS + vj0 + colq * 4);
                v.x *= inv; v.y *= inv; v.z *= inv; v.w *= inv;
                *(float4*)(wbase + (long long)row * NNN + vj0 + colq * 4) = v;
            }

            if (n < 7) TILE_STS((n + 1) & 1);
            if (n < 6) TILE_LDG(V, n + 2);
            __syncthreads();
        }

        // vt dead; region becomes red[]
        #pragma unroll
        for (int rr = 0; rr < 8; rr++)
            #pragma unroll
            for (int c = 0; c < 4; c++)
                *(u64*)(red + kg * 514 + (rg * 8 + rr) * 32 + dg * 8 + 2 * c) = acc2[rr][c];
        __syncthreads();

        const int b = bh >> 3, h = bh & 7;
        #pragma unroll
        for (int s2 = 0; s2 < 2; s2++) {
            int out = t + s2 * 256;
            int row = out >> 5, d = out & 31;
            float sum = 0.f;
            #pragma unroll
            for (int k2 = 0; k2 < 32; k2++) sum += red[k2 * 514 + row * 32 + d];
            sum = sum * rinv[row] + ol[row * 33 + d];
            g_comb[((long long)b * NNN + i0 + row) * CCC + h * DHH + d] = sum;
        }
    }
}

// ============================================================
// Kernel 4: output projection. 128x128 tile, f32x2, pipelined.
// ============================================================
__global__ __launch_bounds__(256) void proj_gemm_kernel(const float* __restrict__ W,
                                                        const float* __restrict__ bias,
                                                        float* __restrict__ out) {
    __shared__ float Xs[2][16 * 132];
    __shared__ float Ws[2][16 * 128];
    const int t  = threadIdx.x;
    const int tx = t & 15, ty = t >> 4;
    const int m0 = blockIdx.y * 128;
    const int n0 = blockIdx.x * 128;

    u64 acc2[8][4] = {};
    float4 px[2], pw[2];
    const int lm = t >> 2, lc = t & 3;
    const int lk = t >> 5, lnq = t & 31;

#define PROJ_LDG(K0) {                                                                  \
        px[0] = *(const float4*)(g_comb + (long long)(m0 + lm) * CCC + (K0) + 4 * lc);  \
        px[1] = *(const float4*)(g_comb + (long long)(m0 + lm + 64) * CCC + (K0) + 4 * lc); \
        pw[0] = *(const float4*)(W + (long long)((K0) + lk) * CCC + n0 + 4 * lnq);      \
        pw[1] = *(const float4*)(W + (long long)((K0) + lk + 8) * CCC + n0 + 4 * lnq); }

    PROJ_LDG(0);
    {
        float* xp = Xs[0]; float* wp = Ws[0];
        xp[(4 * lc + 0) * 132 + lm] = px[0].x;
        xp[(4 * lc + 1) * 132 + lm] = px[0].y;
        xp[(4 * lc + 2) * 132 + lm] = px[0].z;
        xp[(4 * lc + 3) * 132 + lm] = px[0].w;
        xp[(4 * lc + 0) * 132 + lm + 64] = px[1].x;
        xp[(4 * lc + 1) * 132 + lm + 64] = px[1].y;
        xp[(4 * lc + 2) * 132 + lm + 64] = px[1].z;
        xp[(4 * lc + 3) * 132 + lm + 64] = px[1].w;
        *(float4*)(wp + lk * 128 + 4 * lnq) = pw[0];
        *(float4*)(wp + (lk + 8) * 128 + 4 * lnq) = pw[1];
    }
    PROJ_LDG(16);
    __syncthreads();

    for (int kt = 0; kt < 16; kt++) {
        const float* xp = Xs[kt & 1];
        const float* wp = Ws[kt & 1];
        #pragma unroll
        for (int kk = 0; kk < 16; kk++) {
            float4 aa = *(const float4*)(xp + kk * 132 + ty * 8);
            float4 ab = *(const float4*)(xp + kk * 132 + ty * 8 + 4);
            u64 bp[4];
            #pragma unroll
            for (int c = 0; c < 4; c++)
                bp[c] = *(const u64*)(wp + kk * 128 + tx * 2 + 32 * c);
            float av[8] = {aa.x, aa.y, aa.z, aa.w, ab.x, ab.y, ab.z, ab.w};
            #pragma unroll
            for (int r = 0; r < 8; r++) {
                u64 ap = pack2(av[r], av[r]);
                #pragma unroll
                for (int c = 0; c < 4; c++)
                    acc2[r][c] = fma2(ap, bp[c], acc2[r][c]);
            }
        }
        if (kt < 15) {
            float* xp2 = Xs[(kt + 1) & 1]; float* wp2 = Ws[(kt + 1) & 1];
            xp2[(4 * lc + 0) * 132 + lm] = px[0].x;
            xp2[(4 * lc + 1) * 132 + lm] = px[0].y;
            xp2[(4 * lc + 2) * 132 + lm] = px[0].z;
            xp2[(4 * lc + 3) * 132 + lm] = px[0].w;
            xp2[(4 * lc + 0) * 132 + lm + 64] = px[1].x;
            xp2[(4 * lc + 1) * 132 + lm + 64] = px[1].y;
            xp2[(4 * lc + 2) * 132 + lm + 64] = px[1].z;
            xp2[(4 * lc + 3) * 132 + lm + 64] = px[1].w;
            *(float4*)(wp2 + lk * 128 + 4 * lnq) = pw[0];
            *(float4*)(wp2 + (lk + 8) * 128 + 4 * lnq) = pw[1];
        }
        if (kt < 14) PROJ_LDG((kt + 2) * 16);
        __syncthreads();
    }
    #pragma unroll
    for (int r = 0; r < 8; r++) {
        int row = m0 + ty * 8 + r;
        #pragma unroll
        for (int c = 0; c < 4; c++) {
            int col = n0 + tx * 2 + 32 * c;
            float lo, hi;
            unpack2(acc2[r][c], lo, hi);
            *(float2*)(out + (long long)row * CCC + col) =
                make_float2(lo + bias[col], hi + bias[col + 1]);
        }
    }
}

// ============================================================
extern "C" void kernel_launch(void* const* d_in, const int* in_sizes, int n_in,
                              void* d_out, int out_size) {
    const float* x     = (const float*)d_in[0];
    const float* Wqkv  = (const float*)d_in[1];
    const float* Wproj = (const float*)d_in[2];
    const float* bproj = (const float*)d_in[3];
    float* out   = (float*)d_out;
    float* out_w = out + (long long)BB * NNN * CCC;

    cudaFuncSetAttribute(attn_global_kernel,
                         cudaFuncAttributeMaxDynamicSharedMemorySize, ATTN_SMEM);

    qkv_gemm_kernel<<<dim3(6, 64), 256>>>(x, Wqkv);
    attn_global_kernel<<<dim3(NNN / 16, BB * HHH), 256, ATTN_SMEM>>>(out_w);
    proj_gemm_kernel<<<dim3(2, 64), 256>>>(Wproj, bproj, out);
}

// round 11
// speedup vs baseline: 1.1838x; 1.0090x over previous
#include <cuda_runtime.h>

#define BB   4
#define NNN  2048
#define CCC  256
#define HHH  8
#define DHH  32
#define WINW 16
#define SCALE 0.17677669529663687f   // 32^-0.5

typedef unsigned long long u64;

__device__ __forceinline__ u64 fma2(u64 a, u64 b, u64 c) {
    u64 d;
    asm("fma.rn.f32x2 %0, %1, %2, %3;" : "=l"(d) : "l"(a), "l"(b), "l"(c));
    return d;
}
__device__ __forceinline__ u64 pack2(float lo, float hi) {
    u64 d;
    asm("mov.b64 %0, {%1, %2};" : "=l"(d) : "f"(lo), "f"(hi));
    return d;
}
__device__ __forceinline__ float pairsum(u64 p) {
    float lo, hi;
    asm("mov.b64 {%0, %1}, %2;" : "=f"(lo), "=f"(hi) : "l"(p));
    return lo + hi;
}
__device__ __forceinline__ void unpack2(u64 p, float& lo, float& hi) {
    asm("mov.b64 {%0, %1}, %2;" : "=f"(lo), "=f"(hi) : "l"(p));
}

// -------- scratch (device globals; no allocations allowed) --------
__device__ float g_qkv[3LL * BB * HHH * NNN * DHH];   // [3][B][H][N][32]
__device__ float g_comb[(long long)BB * NNN * CCC];   // [B][N][C]

// ============================================================
// Kernel 1: QKV GEMM.  X[8192,256] @ W[256,768] -> scatter to g_qkv
// 128x128 tile, 256 threads, 8x8 microtile, pipelined, 2 CTA/SM.
// ============================================================
__global__ __launch_bounds__(256, 2) void qkv_gemm_kernel(const float* __restrict__ X,
                                                          const float* __restrict__ W) {
    __shared__ float Xs[2][16 * 132];   // Xs[k][m]
    __shared__ float Ws[2][16 * 128];   // Ws[k][n]
    const int t  = threadIdx.x;
    const int tx = t & 15, ty = t >> 4;
    const int m0 = blockIdx.y * 128;
    const int n0 = blockIdx.x * 128;

    u64 acc2[8][4] = {};
    float4 px[2], pw[2];

    const int lm = t >> 2, lc = t & 3;          // X loader coords
    const int lk = t >> 5, lnq = t & 31;        // W loader coords

#define QKV_LDG(K0) {                                                              \
        px[0] = *(const float4*)(X + (long long)(m0 + lm) * CCC + (K0) + 4 * lc);  \
        px[1] = *(const float4*)(X + (long long)(m0 + lm + 64) * CCC + (K0) + 4 * lc); \
        pw[0] = *(const float4*)(W + (long long)((K0) + lk) * 768 + n0 + 4 * lnq); \
        pw[1] = *(const float4*)(W + (long long)((K0) + lk + 8) * 768 + n0 + 4 * lnq); }
#define QKV_STS(BUF) {                                                   \
        float* xp = Xs[BUF]; float* wp = Ws[BUF];                        \
        xp[(4 * lc + 0) * 132 + lm] = px[0].x;                           \
        xp[(4 * lc + 1) * 132 + lm] = px[0].y;                           \
        xp[(4 * lc + 2) * 132 + lm] = px[0].z;                           \
        xp[(4 * lc + 3) * 132 + lm] = px[0].w;                           \
        xp[(4 * lc + 0) * 132 + lm + 64] = px[1].x;                      \
        xp[(4 * lc + 1) * 132 + lm + 64] = px[1].y;                      \
        xp[(4 * lc + 2) * 132 + lm + 64] = px[1].z;                      \
        xp[(4 * lc + 3) * 132 + lm + 64] = px[1].w;                      \
        *(float4*)(wp + lk * 128 + 4 * lnq) = pw[0];                     \
        *(float4*)(wp + (lk + 8) * 128 + 4 * lnq) = pw[1]; }

    QKV_LDG(0); QKV_STS(0); QKV_LDG(16);
    __syncthreads();

    for (int kt = 0; kt < 16; kt++) {
        const float* xp = Xs[kt & 1];
        const float* wp = Ws[kt & 1];
        #pragma unroll
        for (int kk = 0; kk < 16; kk++) {
            float4 aa = *(const float4*)(xp + kk * 132 + ty * 8);
            float4 ab = *(const float4*)(xp + kk * 132 + ty * 8 + 4);
            u64 bp[4];
            #pragma unroll
            for (int c = 0; c < 4; c++)
                bp[c] = *(const u64*)(wp + kk * 128 + tx * 2 + 32 * c);
            float av[8] = {aa.x, aa.y, aa.z, aa.w, ab.x, ab.y, ab.z, ab.w};
            #pragma unroll
            for (int r = 0; r < 8; r++) {
                u64 ap = pack2(av[r], av[r]);
                #pragma unroll
                for (int c = 0; c < 4; c++)
                    acc2[r][c] = fma2(ap, bp[c], acc2[r][c]);
            }
        }
        if (kt < 15) QKV_STS((kt + 1) & 1);
        if (kt < 14) QKV_LDG((kt + 2) * 16);
        __syncthreads();
    }
    #pragma unroll
    for (int r = 0; r < 8; r++) {
        int row = m0 + ty * 8 + r;
        int b   = row >> 11;
        int n   = row & 2047;
        #pragma unroll
        for (int c = 0; c < 4; c++) {
            float lo, hi;
            unpack2(acc2[r][c], lo, hi);
            int col = n0 + tx * 2 + 32 * c;
            #pragma unroll
            for (int j = 0; j < 2; j++) {
                int cc  = col + j;
                int t3  = cc >> 8;
                int rem = cc & 255;
                int h   = rem >> 5;
                int d   = rem & 31;
                g_qkv[((((long long)t3 * BB + b) * HHH + h) * NNN + n) * DHH + d] =
                    (j == 0) ? lo : hi;
            }
        }
    }
}

// ============================================================
// Kernel 2: fused global + local attention per (b,h, 16-row block)
// 256 threads, f32x2, pipelined tiles. P1 keeps q in registers.
// ============================================================
#define SS        2052
#define QS_OFF    (16 * SS)                  // 32832
#define RINV_OFF  (QS_OFF + 16 * 34)         // 33376
#define KB_OFF    (RINV_OFF + 16)            // 33392
#define KTILE     (256 * 34)                 // 8704 floats per buffer
#define SL_OFF    (KB_OFF + 2 * KTILE)       // 50800
#define OL_OFF    (SL_OFF + 16 * 17)         // 51072
#define ATTN_FLOATS (OL_OFF + 16 * 33)       // 51600
#define ATTN_SMEM (ATTN_FLOATS * 4)          // 206400 bytes

__global__ __launch_bounds__(256) void attn_global_kernel(float* __restrict__ out_w) {
    extern __shared__ float sm[];
    float* S    = sm;
    float* qs   = sm + QS_OFF;     // qs[i] stride 34, scale folded
    float* rinv = sm + RINV_OFF;
    float* kb   = sm + KB_OFF;     // double buffer, stride 34
    float* red  = sm + KB_OFF;     // alias: red[kg][514], kg<32
    float* vl   = sm + KB_OFF;     // alias: local V window 16x33
    float* sl   = sm + SL_OFF;
    float* ol   = sm + OL_OFF;

    const int t  = threadIdx.x;
    const int bh = blockIdx.y;
    const int i0 = blockIdx.x * 16;
    const float* Q = g_qkv + (long long)bh * NNN * DHH;
    const float* K = g_qkv + ((long long)BB * HHH + bh) * NNN * DHH;
    const float* V = g_qkv + ((long long)2 * BB * HHH + bh) * NNN * DHH;

    const int plc = t >> 3, plf = t & 7;     // tile loader coords (c, f4)
    float4 pk[8];

#define TILE_LDG(SRC, N) { long long base = (long long)(N) * 256 * DHH;         \
        _Pragma("unroll")                                                       \
        for (int r = 0; r < 8; r++)                                             \
            pk[r] = *(const float4*)((SRC) + base + (long long)(plc + r * 32) * DHH + plf * 4); }
#define TILE_STS(BUF) { float* bp = kb + (BUF) * KTILE;                          \
        _Pragma("unroll")                                                        \
        for (int r = 0; r < 8; r++) {                                            \
            float* p = bp + (plc + r * 32) * 34 + plf * 4;                       \
            *(float2*)(p)     = make_float2(pk[r].x, pk[r].y);                   \
            *(float2*)(p + 2) = make_float2(pk[r].z, pk[r].w); } }

    // ---- packed q (pairs over d, scale folded) ----
    {
        int r = t >> 4, d2 = t & 15;
        float2 qv = *(const float2*)(Q + (long long)(i0 + r) * DHH + 2 * d2);
        *(float2*)(qs + r * 34 + 2 * d2) = make_float2(qv.x * SCALE, qv.y * SCALE);
    }

    // ---------- Phase 1: S = q.K^T  (8 tiles of 256 cols, pipelined) ----------
    {
        const int cg = t & 31, rg = t >> 5;   // 2 rows x 8 cols / thread
        TILE_LDG(K, 0); TILE_STS(0); TILE_LDG(K, 1);
        __syncthreads();

        // q in registers (warp-uniform rows -> broadcast LDS, one-time)
        u64 q2r[2][16];
        #pragma unroll
        for (int r = 0; r < 2; r++)
            #pragma unroll
            for (int d2 = 0; d2 < 16; d2++)
                q2r[r][d2] = *(const u64*)(qs + (rg * 2 + r) * 34 + 2 * d2);

        for (int n = 0; n < 8; n++) {
            const float* bp = kb + (n & 1) * KTILE;
            const int kj0 = n * 256;
            u64 acc2[2][8] = {};
            #pragma unroll
            for (int d2 = 0; d2 < 16; d2++) {
                u64 k2[8];
                #pragma unroll
                for (int c = 0; c < 8; c++)
                    k2[c] = *(const u64*)(bp + (cg + 32 * c) * 34 + 2 * d2);
                #pragma unroll
                for (int r = 0; r < 2; r++)
                    #pragma unroll
                    for (int c = 0; c < 8; c++)
                        acc2[r][c] = fma2(q2r[r][d2], k2[c], acc2[r][c]);
            }
            #pragma unroll
            for (int r = 0; r < 2; r++)
                #pragma unroll
                for (int c = 0; c < 8; c++)
                    S[(rg * 2 + r) * SS + kj0 + cg + 32 * c] = pairsum(acc2[r][c]);
            if (n < 7) TILE_STS((n + 1) & 1);
            if (n < 6) TILE_LDG(K, n + 2);
            __syncthreads();
        }
    }

    // ---------- Local window attention (block == window), raw S subtile ----------
    {
        #pragma unroll
        for (int r = 0; r < 2; r++) {
            int idx = t + r * 256;
            int i = idx >> 5, d = idx & 31;
            vl[i * 33 + d] = V[(long long)(i0 + i) * DHH + d];
        }
        {
            int row = t >> 4, j = t & 15;
            float s = S[row * SS + i0 + j];
            float m = s;
            #pragma unroll
            for (int o = 8; o; o >>= 1) m = fmaxf(m, __shfl_xor_sync(0xffffffffu, m, o, 16));
            float e = __expf(s - m);
            float ssum = e;
            #pragma unroll
            for (int o = 8; o; o >>= 1) ssum += __shfl_xor_sync(0xffffffffu, ssum, o, 16);
            sl[row * 17 + j] = e / ssum;
        }
        __syncthreads();
        #pragma unroll
        for (int r = 0; r < 2; r++) {
            int idx = t + r * 256;
            int row = idx >> 5, d = idx & 31;
            float a = 0.f;
            #pragma unroll
            for (int j = 0; j < 16; j++) a += sl[row * 17 + j] * vl[j * 33 + d];
            ol[row * 33 + d] = a;
        }
    }
    __syncthreads();

    // ---------- Phase 2: softmax stats (16 lanes/row); S := e ----------
    {
        int row = t >> 4, lane = t & 15;
        float* Sr = S + row * SS;
        float m = -1e30f;
        #pragma unroll 8
        for (int i = 0; i < 32; i++) {
            float4 v = *(const float4*)(Sr + i * 64 + lane * 4);
            m = fmaxf(m, fmaxf(fmaxf(v.x, v.y), fmaxf(v.z, v.w)));
        }
        #pragma unroll
        for (int o = 8; o; o >>= 1) m = fmaxf(m, __shfl_xor_sync(0xffffffffu, m, o, 16));
        float ssum = 0.f;
        #pragma unroll 8
        for (int i = 0; i < 32; i++) {
            float4 v = *(float4*)(Sr + i * 64 + lane * 4);
            v.x = __expf(v.x - m); v.y = __expf(v.y - m);
            v.z = __expf(v.z - m); v.w = __expf(v.w - m);
            *(float4*)(Sr + i * 64 + lane * 4) = v;
            ssum += (v.x + v.y) + (v.z + v.w);
        }
        #pragma unroll
        for (int o = 8; o; o >>= 1) ssum += __shfl_xor_sync(0xffffffffu, ssum, o, 16);
        if (lane == 0) rinv[row] = 1.0f / ssum;
    }
    __syncthreads();

    // ---------- Phase 3: weights write + O = e.V  (8 tiles of 256 rows) ----------
    {
        const int kg = t & 31;           // split-k 32
        const int dg = (t >> 5) & 3;     // 8 dims (4 pairs)
        const int rg = t >> 7;           // 2 groups of 8 rows
        u64 acc2[8][4] = {};
        float* wbase = out_w + (long long)bh * NNN * NNN + (long long)i0 * NNN;

        TILE_LDG(V, 0); TILE_STS(0); TILE_LDG(V, 1);
        __syncthreads();
        for (int n = 0; n < 8; n++) {
            const float* vb = kb + (n & 1) * KTILE;
            const int vj0 = n * 256;

            #pragma unroll
            for (int i = 0; i < 8; i++) {
                int kl = i * 32 + kg;
                u64 v2[4];
                #pragma unroll
                for (int c = 0; c < 4; c++)
                    v2[c] = *(const u64*)(vb + kl * 34 + dg * 8 + 2 * c);
                #pragma unroll
                for (int rr = 0; rr < 8; rr++) {
                    float s = S[(rg * 8 + rr) * SS + vj0 + kl];
                    u64 sp = pack2(s, s);
                    #pragma unroll
                    for (int c = 0; c < 4; c++)
                        acc2[rr][c] = fma2(sp, v2[c], acc2[rr][c]);
                }
            }

            // write normalized weights for this column chunk (STG drains async)
            #pragma unroll
            for (int s2 = 0; s2 < 4; s2++) {
                int idx = t + s2 * 256;
                int row = idx >> 6, colq = idx & 63;
                float inv = rinv[row];
                float4 v = *(const float4*)(S + row * SS + vj0 + colq * 4);
                v.x *= inv; v.y *= inv; v.z *= inv; v.w *= inv;
                *(float4*)(wbase + (long long)row * NNN + vj0 + colq * 4) = v;
            }

            if (n < 7) TILE_STS((n + 1) & 1);
            if (n < 6) TILE_LDG(V, n + 2);
            __syncthreads();
        }

        // vt dead; region becomes red[]
        #pragma unroll
        for (int rr = 0; rr < 8; rr++)
            #pragma unroll
            for (int c = 0; c < 4; c++)
                *(u64*)(red + kg * 514 + (rg * 8 + rr) * 32 + dg * 8 + 2 * c) = acc2[rr][c];
        __syncthreads();

        const int b = bh >> 3, h = bh & 7;
        #pragma unroll
        for (int s2 = 0; s2 < 2; s2++) {
            int out = t + s2 * 256;
            int row = out >> 5, d = out & 31;
            float sum = 0.f;
            #pragma unroll
            for (int k2 = 0; k2 < 32; k2++) sum += red[k2 * 514 + row * 32 + d];
            sum = sum * rinv[row] + ol[row * 33 + d];
            g_comb[((long long)b * NNN + i0 + row) * CCC + h * DHH + d] = sum;
        }
    }
}

// ============================================================
// Kernel 4: output projection. 128x128 tile, f32x2, pipelined, 2 CTA/SM.
// ============================================================
__global__ __launch_bounds__(256, 2) void proj_gemm_kernel(const float* __restrict__ W,
                                                           const float* __restrict__ bias,
                                                           float* __restrict__ out) {
    __shared__ float Xs[2][16 * 132];
    __shared__ float Ws[2][16 * 128];
    const int t  = threadIdx.x;
    const int tx = t & 15, ty = t >> 4;
    const int m0 = blockIdx.y * 128;
    const int n0 = blockIdx.x * 128;

    u64 acc2[8][4] = {};
    float4 px[2], pw[2];
    const int lm = t >> 2, lc = t & 3;
    const int lk = t >> 5, lnq = t & 31;

#define PROJ_LDG(K0) {                                                                  \
        px[0] = *(const float4*)(g_comb + (long long)(m0 + lm) * CCC + (K0) + 4 * lc);  \
        px[1] = *(const float4*)(g_comb + (long long)(m0 + lm + 64) * CCC + (K0) + 4 * lc); \
        pw[0] = *(const float4*)(W + (long long)((K0) + lk) * CCC + n0 + 4 * lnq);      \
        pw[1] = *(const float4*)(W + (long long)((K0) + lk + 8) * CCC + n0 + 4 * lnq); }
#define PROJ_STS(BUF) {                                                  \
        float* xp = Xs[BUF]; float* wp = Ws[BUF];                        \
        xp[(4 * lc + 0) * 132 + lm] = px[0].x;                           \
        xp[(4 * lc + 1) * 132 + lm] = px[0].y;                           \
        xp[(4 * lc + 2) * 132 + lm] = px[0].z;                           \
        xp[(4 * lc + 3) * 132 + lm] = px[0].w;                           \
        xp[(4 * lc + 0) * 132 + lm + 64] = px[1].x;                      \
        xp[(4 * lc + 1) * 132 + lm + 64] = px[1].y;                      \
        xp[(4 * lc + 2) * 132 + lm + 64] = px[1].z;                      \
        xp[(4 * lc + 3) * 132 + lm + 64] = px[1].w;                      \
        *(float4*)(wp + lk * 128 + 4 * lnq) = pw[0];                     \
        *(float4*)(wp + (lk + 8) * 128 + 4 * lnq) = pw[1]; }

    PROJ_LDG(0); PROJ_STS(0); PROJ_LDG(16);
    __syncthreads();

    for (int kt = 0; kt < 16; kt++) {
        const float* xp = Xs[kt & 1];
        const float* wp = Ws[kt & 1];
        #pragma unroll
        for (int kk = 0; kk < 16; kk++) {
            float4 aa = *(const float4*)(xp + kk * 132 + ty * 8);
            float4 ab = *(const float4*)(xp + kk * 132 + ty * 8 + 4);
            u64 bp[4];
            #pragma unroll
            for (int c = 0; c < 4; c++)
                bp[c] = *(const u64*)(wp + kk * 128 + tx * 2 + 32 * c);
            float av[8] = {aa.x, aa.y, aa.z, aa.w, ab.x, ab.y, ab.z, ab.w};
            #pragma unroll
            for (int r = 0; r < 8; r++) {
                u64 ap = pack2(av[r], av[r]);
                #pragma unroll
                for (int c = 0; c < 4; c++)
                    acc2[r][c] = fma2(ap, bp[c], acc2[r][c]);
            }
        }
        if (kt < 15) PROJ_STS((kt + 1) & 1);
        if (kt < 14) PROJ_LDG((kt + 2) * 16);
        __syncthreads();
    }
    #pragma unroll
    for (int r = 0; r < 8; r++) {
        int row = m0 + ty * 8 + r;
        #pragma unroll
        for (int c = 0; c < 4; c++) {
            int col = n0 + tx * 2 + 32 * c;
            float lo, hi;
            unpack2(acc2[r][c], lo, hi);
            *(float2*)(out + (long long)row * CCC + col) =
                make_float2(lo + bias[col], hi + bias[col + 1]);
        }
    }
}

// ============================================================
extern "C" void kernel_launch(void* const* d_in, const int* in_sizes, int n_in,
                              void* d_out, int out_size) {
    const float* x     = (const float*)d_in[0];
    const float* Wqkv  = (const float*)d_in[1];
    const float* Wproj = (const float*)d_in[2];
    const float* bproj = (const float*)d_in[3];
    float* out   = (float*)d_out;
    float* out_w = out + (long long)BB * NNN * CCC;

    cudaFuncSetAttribute(attn_global_kernel,
                         cudaFuncAttributeMaxDynamicSharedMemorySize, ATTN_SMEM);

    qkv_gemm_kernel<<<dim3(6, 64), 256>>>(x, Wqkv);
    attn_global_kernel<<<dim3(NNN / 16, BB * HHH), 256, ATTN_SMEM>>>(out_w);
    proj_gemm_kernel<<<dim3(2, 64), 256>>>(Wproj, bproj, out);
}

// round 12
// speedup vs baseline: 1.1932x; 1.0080x over previous
#include <cuda_runtime.h>

#define BB   4
#define NNN  2048
#define CCC  256
#define HHH  8
#define DHH  32
#define WINW 16
#define SCALE 0.17677669529663687f   // 32^-0.5

typedef unsigned long long u64;

__device__ __forceinline__ u64 fma2(u64 a, u64 b, u64 c) {
    u64 d;
    asm("fma.rn.f32x2 %0, %1, %2, %3;" : "=l"(d) : "l"(a), "l"(b), "l"(c));
    return d;
}
__device__ __forceinline__ u64 pack2(float lo, float hi) {
    u64 d;
    asm("mov.b64 %0, {%1, %2};" : "=l"(d) : "f"(lo), "f"(hi));
    return d;
}
__device__ __forceinline__ float pairsum(u64 p) {
    float lo, hi;
    asm("mov.b64 {%0, %1}, %2;" : "=f"(lo), "=f"(hi) : "l"(p));
    return lo + hi;
}
__device__ __forceinline__ void unpack2(u64 p, float& lo, float& hi) {
    asm("mov.b64 {%0, %1}, %2;" : "=f"(lo), "=f"(hi) : "l"(p));
}

// -------- scratch (device globals; no allocations allowed) --------
__device__ float g_qkv[3LL * BB * HHH * NNN * DHH];   // [3][B][H][N][32]
__device__ float g_comb[(long long)BB * NNN * CCC];   // [B][N][C]

// ============================================================
// Kernel 1: QKV GEMM.  X[8192,256] @ W[256,768] -> scatter to g_qkv
// 64x128 tile, 256 threads, 4x8 microtile, pipelined, 3 CTA/SM.
// ============================================================
__global__ __launch_bounds__(256, 3) void qkv_gemm_kernel(const float* __restrict__ X,
                                                          const float* __restrict__ W) {
    __shared__ float Xs[2][16 * 68];    // Xs[k][m]
    __shared__ float Ws[2][16 * 128];   // Ws[k][n]
    const int t  = threadIdx.x;
    const int tx = t & 15, ty = t >> 4;
    const int m0 = blockIdx.y * 64;
    const int n0 = blockIdx.x * 128;

    u64 acc2[4][4] = {};
    float4 px, pw[2];

    const int lm = t >> 2, lc = t & 3;          // X loader coords (64 rows x 4 f4)
    const int lk = t >> 5, lnq = t & 31;        // W loader coords

#define QKV_LDG(K0) {                                                              \
        px    = *(const float4*)(X + (long long)(m0 + lm) * CCC + (K0) + 4 * lc);  \
        pw[0] = *(const float4*)(W + (long long)((K0) + lk) * 768 + n0 + 4 * lnq); \
        pw[1] = *(const float4*)(W + (long long)((K0) + lk + 8) * 768 + n0 + 4 * lnq); }
#define QKV_STS(BUF) {                                                   \
        float* xp = Xs[BUF]; float* wp = Ws[BUF];                        \
        xp[(4 * lc + 0) * 68 + lm] = px.x;                               \
        xp[(4 * lc + 1) * 68 + lm] = px.y;                               \
        xp[(4 * lc + 2) * 68 + lm] = px.z;                               \
        xp[(4 * lc + 3) * 68 + lm] = px.w;                               \
        *(float4*)(wp + lk * 128 + 4 * lnq) = pw[0];                     \
        *(float4*)(wp + (lk + 8) * 128 + 4 * lnq) = pw[1]; }

    QKV_LDG(0); QKV_STS(0); QKV_LDG(16);
    __syncthreads();

    for (int kt = 0; kt < 16; kt++) {
        const float* xp = Xs[kt & 1];
        const float* wp = Ws[kt & 1];
        #pragma unroll
        for (int kk = 0; kk < 16; kk++) {
            float4 aa = *(const float4*)(xp + kk * 68 + ty * 4);
            u64 bp[4];
            #pragma unroll
            for (int c = 0; c < 4; c++)
                bp[c] = *(const u64*)(wp + kk * 128 + tx * 2 + 32 * c);
            float av[4] = {aa.x, aa.y, aa.z, aa.w};
            #pragma unroll
            for (int r = 0; r < 4; r++) {
                u64 ap = pack2(av[r], av[r]);
                #pragma unroll
                for (int c = 0; c < 4; c++)
                    acc2[r][c] = fma2(ap, bp[c], acc2[r][c]);
            }
        }
        if (kt < 15) QKV_STS((kt + 1) & 1);
        if (kt < 14) QKV_LDG((kt + 2) * 16);
        __syncthreads();
    }
    #pragma unroll
    for (int r = 0; r < 4; r++) {
        int row = m0 + ty * 4 + r;
        int b   = row >> 11;
        int n   = row & 2047;
        #pragma unroll
        for (int c = 0; c < 4; c++) {
            float lo, hi;
            unpack2(acc2[r][c], lo, hi);
            int col = n0 + tx * 2 + 32 * c;
            #pragma unroll
            for (int j = 0; j < 2; j++) {
                int cc  = col + j;
                int t3  = cc >> 8;
                int rem = cc & 255;
                int h   = rem >> 5;
                int d   = rem & 31;
                g_qkv[((((long long)t3 * BB + b) * HHH + h) * NNN + n) * DHH + d] =
                    (j == 0) ? lo : hi;
            }
        }
    }
}

// ============================================================
// Kernel 2: fused global + local attention per (b,h, 16-row block)
// 256 threads, f32x2, pipelined tiles. P1 4x4 microtile (crossbar-optimal).
// ============================================================
#define SS        2052
#define QS_OFF    (16 * SS)                  // 32832
#define RINV_OFF  (QS_OFF + 16 * 34)         // 33376
#define KB_OFF    (RINV_OFF + 16)            // 33392
#define KTILE     (256 * 34)                 // 8704 floats per buffer
#define SL_OFF    (KB_OFF + 2 * KTILE)       // 50800
#define OL_OFF    (SL_OFF + 16 * 17)         // 51072
#define ATTN_FLOATS (OL_OFF + 16 * 33)       // 51600
#define ATTN_SMEM (ATTN_FLOATS * 4)          // 206400 bytes

__global__ __launch_bounds__(256) void attn_global_kernel(float* __restrict__ out_w) {
    extern __shared__ float sm[];
    float* S    = sm;
    float* qs   = sm + QS_OFF;     // qs[i] stride 34, scale folded
    float* rinv = sm + RINV_OFF;
    float* kb   = sm + KB_OFF;     // double buffer, stride 34
    float* red  = sm + KB_OFF;     // alias: red[kg][514], kg<32
    float* vl   = sm + KB_OFF;     // alias: local V window 16x33
    float* sl   = sm + SL_OFF;
    float* ol   = sm + OL_OFF;

    const int t  = threadIdx.x;
    const int bh = blockIdx.y;
    const int i0 = blockIdx.x * 16;
    const float* Q = g_qkv + (long long)bh * NNN * DHH;
    const float* K = g_qkv + ((long long)BB * HHH + bh) * NNN * DHH;
    const float* V = g_qkv + ((long long)2 * BB * HHH + bh) * NNN * DHH;

    const int plc = t >> 3, plf = t & 7;     // tile loader coords (c, f4)
    float4 pk[8];

#define TILE_LDG(SRC, N) { long long base = (long long)(N) * 256 * DHH;         \
        _Pragma("unroll")                                                       \
        for (int r = 0; r < 8; r++)                                             \
            pk[r] = *(const float4*)((SRC) + base + (long long)(plc + r * 32) * DHH + plf * 4); }
#define TILE_STS(BUF) { float* bp = kb + (BUF) * KTILE;                          \
        _Pragma("unroll")                                                        \
        for (int r = 0; r < 8; r++) {                                            \
            float* p = bp + (plc + r * 32) * 34 + plf * 4;                       \
            *(float2*)(p)     = make_float2(pk[r].x, pk[r].y);                   \
            *(float2*)(p + 2) = make_float2(pk[r].z, pk[r].w); } }

    // ---- packed q (pairs over d, scale folded) ----
    {
        int r = t >> 4, d2 = t & 15;
        float2 qv = *(const float2*)(Q + (long long)(i0 + r) * DHH + 2 * d2);
        *(float2*)(qs + r * 34 + 2 * d2) = make_float2(qv.x * SCALE, qv.y * SCALE);
    }

    // ---------- Phase 1: S = q.K^T  (8 tiles of 256 cols, pipelined) ----------
    {
        const int cg = t & 63, rg = t >> 6;   // 4 rows x 4 cols / thread
        TILE_LDG(K, 0); TILE_STS(0); TILE_LDG(K, 1);
        __syncthreads();
        for (int n = 0; n < 8; n++) {
            const float* bp = kb + (n & 1) * KTILE;
            const int kj0 = n * 256;
            u64 acc2[4][4] = {};
            #pragma unroll
            for (int d2 = 0; d2 < 16; d2++) {
                u64 k2[4];
                #pragma unroll
                for (int c = 0; c < 4; c++)
                    k2[c] = *(const u64*)(bp + (cg + 64 * c) * 34 + 2 * d2);
                #pragma unroll
                for (int r = 0; r < 4; r++) {
                    u64 q2 = *(const u64*)(qs + (rg * 4 + r) * 34 + 2 * d2);  // bcast
                    #pragma unroll
                    for (int c = 0; c < 4; c++)
                        acc2[r][c] = fma2(q2, k2[c], acc2[r][c]);
                }
            }
            #pragma unroll
            for (int r = 0; r < 4; r++)
                #pragma unroll
                for (int c = 0; c < 4; c++)
                    S[(rg * 4 + r) * SS + kj0 + cg + 64 * c] = pairsum(acc2[r][c]);
            if (n < 7) TILE_STS((n + 1) & 1);
            if (n < 6) TILE_LDG(K, n + 2);
            __syncthreads();
        }
    }

    // ---------- Local window attention (block == window), raw S subtile ----------
    {
        #pragma unroll
        for (int r = 0; r < 2; r++) {
            int idx = t + r * 256;
            int i = idx >> 5, d = idx & 31;
            vl[i * 33 + d] = V[(long long)(i0 + i) * DHH + d];
        }
        {
            int row = t >> 4, j = t & 15;
            float s = S[row * SS + i0 + j];
            float m = s;
            #pragma unroll
            for (int o = 8; o; o >>= 1) m = fmaxf(m, __shfl_xor_sync(0xffffffffu, m, o, 16));
            float e = __expf(s - m);
            float ssum = e;
            #pragma unroll
            for (int o = 8; o; o >>= 1) ssum += __shfl_xor_sync(0xffffffffu, ssum, o, 16);
            sl[row * 17 + j] = e / ssum;
        }
        __syncthreads();
        #pragma unroll
        for (int r = 0; r < 2; r++) {
            int idx = t + r * 256;
            int row = idx >> 5, d = idx & 31;
            float a = 0.f;
            #pragma unroll
            for (int j = 0; j < 16; j++) a += sl[row * 17 + j] * vl[j * 33 + d];
            ol[row * 33 + d] = a;
        }
    }
    __syncthreads();

    // ---------- Phase 2: softmax stats (16 lanes/row); S := e ----------
    {
        int row = t >> 4, lane = t & 15;
        float* Sr = S + row * SS;
        float m = -1e30f;
        #pragma unroll 8
        for (int i = 0; i < 32; i++) {
            float4 v = *(const float4*)(Sr + i * 64 + lane * 4);
            m = fmaxf(m, fmaxf(fmaxf(v.x, v.y), fmaxf(v.z, v.w)));
        }
        #pragma unroll
        for (int o = 8; o; o >>= 1) m = fmaxf(m, __shfl_xor_sync(0xffffffffu, m, o, 16));
        float ssum = 0.f;
        #pragma unroll 8
        for (int i = 0; i < 32; i++) {
            float4 v = *(float4*)(Sr + i * 64 + lane * 4);
            v.x = __expf(v.x - m); v.y = __expf(v.y - m);
            v.z = __expf(v.z - m); v.w = __expf(v.w - m);
            *(float4*)(Sr + i * 64 + lane * 4) = v;
            ssum += (v.x + v.y) + (v.z + v.w);
        }
        #pragma unroll
        for (int o = 8; o; o >>= 1) ssum += __shfl_xor_sync(0xffffffffu, ssum, o, 16);
        if (lane == 0) rinv[row] = 1.0f / ssum;
    }
    __syncthreads();

    // ---------- Phase 3: weights write + O = e.V  (8 tiles of 256 rows) ----------
    {
        const int kg = t & 31;           // split-k 32
        const int dg = (t >> 5) & 3;     // 8 dims (4 pairs)
        const int rg = t >> 7;           // 2 groups of 8 rows
        u64 acc2[8][4] = {};
        float* wbase = out_w + (long long)bh * NNN * NNN + (long long)i0 * NNN;

        TILE_LDG(V, 0); TILE_STS(0); TILE_LDG(V, 1);
        __syncthreads();
        for (int n = 0; n < 8; n++) {
            const float* vb = kb + (n & 1) * KTILE;
            const int vj0 = n * 256;

            #pragma unroll
            for (int i = 0; i < 8; i++) {
                int kl = i * 32 + kg;
                u64 v2[4];
                #pragma unroll
                for (int c = 0; c < 4; c++)
                    v2[c] = *(const u64*)(vb + kl * 34 + dg * 8 + 2 * c);
                #pragma unroll
                for (int rr = 0; rr < 8; rr++) {
                    float s = S[(rg * 8 + rr) * SS + vj0 + kl];
                    u64 sp = pack2(s, s);
                    #pragma unroll
                    for (int c = 0; c < 4; c++)
                        acc2[rr][c] = fma2(sp, v2[c], acc2[rr][c]);
                }
            }

            // write normalized weights for this column chunk (STG drains async)
            #pragma unroll
            for (int s2 = 0; s2 < 4; s2++) {
                int idx = t + s2 * 256;
                int row = idx >> 6, colq = idx & 63;
                float inv = rinv[row];
                float4 v = *(const float4*)(S + row * SS + vj0 + colq * 4);
                v.x *= inv; v.y *= inv; v.z *= inv; v.w *= inv;
                *(float4*)(wbase + (long long)row * NNN + vj0 + colq * 4) = v;
            }

            if (n < 7) TILE_STS((n + 1) & 1);
            if (n < 6) TILE_LDG(V, n + 2);
            __syncthreads();
        }

        // vt dead; region becomes red[]
        #pragma unroll
        for (int rr = 0; rr < 8; rr++)
            #pragma unroll
            for (int c = 0; c < 4; c++)
                *(u64*)(red + kg * 514 + (rg * 8 + rr) * 32 + dg * 8 + 2 * c) = acc2[rr][c];
        __syncthreads();

        const int b = bh >> 3, h = bh & 7;
        #pragma unroll
        for (int s2 = 0; s2 < 2; s2++) {
            int out = t + s2 * 256;
            int row = out >> 5, d = out & 31;
            float sum = 0.f;
            #pragma unroll
            for (int k2 = 0; k2 < 32; k2++) sum += red[k2 * 514 + row * 32 + d];
            sum = sum * rinv[row] + ol[row * 33 + d];
            g_comb[((long long)b * NNN + i0 + row) * CCC + h * DHH + d] = sum;
        }
    }
}

// ============================================================
// Kernel 4: output projection. 64x128 tile, f32x2, pipelined, 3 CTA/SM.
// ============================================================
__global__ __launch_bounds__(256, 3) void proj_gemm_kernel(const float* __restrict__ W,
                                                           const float* __restrict__ bias,
                                                           float* __restrict__ out) {
    __shared__ float Xs[2][16 * 68];
    __shared__ float Ws[2][16 * 128];
    const int t  = threadIdx.x;
    const int tx = t & 15, ty = t >> 4;
    const int m0 = blockIdx.y * 64;
    const int n0 = blockIdx.x * 128;

    u64 acc2[4][4] = {};
    float4 px, pw[2];
    const int lm = t >> 2, lc = t & 3;
    const int lk = t >> 5, lnq = t & 31;

#define PROJ_LDG(K0) {                                                                  \
        px    = *(const float4*)(g_comb + (long long)(m0 + lm) * CCC + (K0) + 4 * lc);  \
        pw[0] = *(const float4*)(W + (long long)((K0) + lk) * CCC + n0 + 4 * lnq);      \
        pw[1] = *(const float4*)(W + (long long)((K0) + lk + 8) * CCC + n0 + 4 * lnq); }
#define PROJ_STS(BUF) {                                                  \
        float* xp = Xs[BUF]; float* wp = Ws[BUF];                        \
        xp[(4 * lc + 0) * 68 + lm] = px.x;                               \
        xp[(4 * lc + 1) * 68 + lm] = px.y;                               \
        xp[(4 * lc + 2) * 68 + lm] = px.z;                               \
        xp[(4 * lc + 3) * 68 + lm] = px.w;                               \
        *(float4*)(wp + lk * 128 + 4 * lnq) = pw[0];                     \
        *(float4*)(wp + (lk + 8) * 128 + 4 * lnq) = pw[1]; }

    PROJ_LDG(0); PROJ_STS(0); PROJ_LDG(16);
    __syncthreads();

    for (int kt = 0; kt < 16; kt++) {
        const float* xp = Xs[kt & 1];
        const float* wp = Ws[kt & 1];
        #pragma unroll
        for (int kk = 0; kk < 16; kk++) {
            float4 aa = *(const float4*)(xp + kk * 68 + ty * 4);
            u64 bp[4];
            #pragma unroll
            for (int c = 0; c < 4; c++)
                bp[c] = *(const u64*)(wp + kk * 128 + tx * 2 + 32 * c);
            float av[4] = {aa.x, aa.y, aa.z, aa.w};
            #pragma unroll
            for (int r = 0; r < 4; r++) {
                u64 ap = pack2(av[r], av[r]);
                #pragma unroll
                for (int c = 0; c < 4; c++)
                    acc2[r][c] = fma2(ap, bp[c], acc2[r][c]);
            }
        }
        if (kt < 15) PROJ_STS((kt + 1) & 1);
        if (kt < 14) PROJ_LDG((kt + 2) * 16);
        __syncthreads();
    }
    #pragma unroll
    for (int r = 0; r < 4; r++) {
        int row = m0 + ty * 4 + r;
        #pragma unroll
        for (int c = 0; c < 4; c++) {
            int col = n0 + tx * 2 + 32 * c;
            float lo, hi;
            unpack2(acc2[r][c], lo, hi);
            *(float2*)(out + (long long)row * CCC + col) =
                make_float2(lo + bias[col], hi + bias[col + 1]);
        }
    }
}

// ============================================================
extern "C" void kernel_launch(void* const* d_in, const int* in_sizes, int n_in,
                              void* d_out, int out_size) {
    const float* x     = (const float*)d_in[0];
    const float* Wqkv  = (const float*)d_in[1];
    const float* Wproj = (const float*)d_in[2];
    const float* bproj = (const float*)d_in[3];
    float* out   = (float*)d_out;
    float* out_w = out + (long long)BB * NNN * CCC;

    cudaFuncSetAttribute(attn_global_kernel,
                         cudaFuncAttributeMaxDynamicSharedMemorySize, ATTN_SMEM);

    qkv_gemm_kernel<<<dim3(6, 128), 256>>>(x, Wqkv);
    attn_global_kernel<<<dim3(NNN / 16, BB * HHH), 256, ATTN_SMEM>>>(out_w);
    proj_gemm_kernel<<<dim3(2, 128), 256>>>(Wproj, bproj, out);
}

// round 13
// speedup vs baseline: 1.2956x; 1.0858x over previous
#include <cuda_runtime.h>

#define BB   4
#define NNN  2048
#define CCC  256
#define HHH  8
#define DHH  32
#define WINW 16
#define SCALE 0.17677669529663687f   // 32^-0.5

typedef unsigned long long u64;

__device__ __forceinline__ u64 fma2(u64 a, u64 b, u64 c) {
    u64 d;
    asm("fma.rn.f32x2 %0, %1, %2, %3;" : "=l"(d) : "l"(a), "l"(b), "l"(c));
    return d;
}
__device__ __forceinline__ u64 pack2(float lo, float hi) {
    u64 d;
    asm("mov.b64 %0, {%1, %2};" : "=l"(d) : "f"(lo), "f"(hi));
    return d;
}
__device__ __forceinline__ float pairsum(u64 p) {
    float lo, hi;
    asm("mov.b64 {%0, %1}, %2;" : "=f"(lo), "=f"(hi) : "l"(p));
    return lo + hi;
}
__device__ __forceinline__ void unpack2(u64 p, float& lo, float& hi) {
    asm("mov.b64 {%0, %1}, %2;" : "=f"(lo), "=f"(hi) : "l"(p));
}

// -------- scratch (device globals; no allocations allowed) --------
__device__ float g_qkv[3LL * BB * HHH * NNN * DHH];   // [3][B][H][N][32]
__device__ float g_comb[(long long)BB * NNN * CCC];   // [B][N][C]

// ============================================================
// Kernel 1: QKV GEMM.  X[8192,256] @ W[256,768] -> scatter to g_qkv
// 128x128 tile, 256 threads, 8x8 microtile, pipelined, 2 CTA/SM.  (R11 proven)
// ============================================================
__global__ __launch_bounds__(256, 2) void qkv_gemm_kernel(const float* __restrict__ X,
                                                          const float* __restrict__ W) {
    __shared__ float Xs[2][16 * 132];   // Xs[k][m]
    __shared__ float Ws[2][16 * 128];   // Ws[k][n]
    const int t  = threadIdx.x;
    const int tx = t & 15, ty = t >> 4;
    const int m0 = blockIdx.y * 128;
    const int n0 = blockIdx.x * 128;

    u64 acc2[8][4] = {};
    float4 px[2], pw[2];

    const int lm = t >> 2, lc = t & 3;          // X loader coords
    const int lk = t >> 5, lnq = t & 31;        // W loader coords

#define QKV_LDG(K0) {                                                              \
        px[0] = *(const float4*)(X + (long long)(m0 + lm) * CCC + (K0) + 4 * lc);  \
        px[1] = *(const float4*)(X + (long long)(m0 + lm + 64) * CCC + (K0) + 4 * lc); \
        pw[0] = *(const float4*)(W + (long long)((K0) + lk) * 768 + n0 + 4 * lnq); \
        pw[1] = *(const float4*)(W + (long long)((K0) + lk + 8) * 768 + n0 + 4 * lnq); }
#define QKV_STS(BUF) {                                                   \
        float* xp = Xs[BUF]; float* wp = Ws[BUF];                        \
        xp[(4 * lc + 0) * 132 + lm] = px[0].x;                           \
        xp[(4 * lc + 1) * 132 + lm] = px[0].y;                           \
        xp[(4 * lc + 2) * 132 + lm] = px[0].z;                           \
        xp[(4 * lc + 3) * 132 + lm] = px[0].w;                           \
        xp[(4 * lc + 0) * 132 + lm + 64] = px[1].x;                      \
        xp[(4 * lc + 1) * 132 + lm + 64] = px[1].y;                      \
        xp[(4 * lc + 2) * 132 + lm + 64] = px[1].z;                      \
        xp[(4 * lc + 3) * 132 + lm + 64] = px[1].w;                      \
        *(float4*)(wp + lk * 128 + 4 * lnq) = pw[0];                     \
        *(float4*)(wp + (lk + 8) * 128 + 4 * lnq) = pw[1]; }

    QKV_LDG(0); QKV_STS(0); QKV_LDG(16);
    __syncthreads();

    for (int kt = 0; kt < 16; kt++) {
        const float* xp = Xs[kt & 1];
        const float* wp = Ws[kt & 1];
        #pragma unroll
        for (int kk = 0; kk < 16; kk++) {
            float4 aa = *(const float4*)(xp + kk * 132 + ty * 8);
            float4 ab = *(const float4*)(xp + kk * 132 + ty * 8 + 4);
            u64 bp[4];
            #pragma unroll
            for (int c = 0; c < 4; c++)
                bp[c] = *(const u64*)(wp + kk * 128 + tx * 2 + 32 * c);
            float av[8] = {aa.x, aa.y, aa.z, aa.w, ab.x, ab.y, ab.z, ab.w};
            #pragma unroll
            for (int r = 0; r < 8; r++) {
                u64 ap = pack2(av[r], av[r]);
                #pragma unroll
                for (int c = 0; c < 4; c++)
                    acc2[r][c] = fma2(ap, bp[c], acc2[r][c]);
            }
        }
        if (kt < 15) QKV_STS((kt + 1) & 1);
        if (kt < 14) QKV_LDG((kt + 2) * 16);
        __syncthreads();
    }
    #pragma unroll
    for (int r = 0; r < 8; r++) {
        int row = m0 + ty * 8 + r;
        int b   = row >> 11;
        int n   = row & 2047;
        #pragma unroll
        for (int c = 0; c < 4; c++) {
            float lo, hi;
            unpack2(acc2[r][c], lo, hi);
            int col = n0 + tx * 2 + 32 * c;
            #pragma unroll
            for (int j = 0; j < 2; j++) {
                int cc  = col + j;
                int t3  = cc >> 8;
                int rem = cc & 255;
                int h   = rem >> 5;
                int d   = rem & 31;
                g_qkv[((((long long)t3 * BB + b) * HHH + h) * NNN + n) * DHH + d] =
                    (j == 0) ? lo : hi;
            }
        }
    }
}

// ============================================================
// Kernel 2: fused global + local attention per (b,h, 16-row block)
// 256 threads. P1: 256-row K tiles (pk[8]). P3: 128-row V tiles (pk[4],
// low register pressure, no spills).
// ============================================================
#define SS        2052
#define QS_OFF    (16 * SS)                  // 32832
#define RINV_OFF  (QS_OFF + 16 * 34)         // 33376
#define KB_OFF    (RINV_OFF + 16)            // 33392
#define KTILE     (256 * 34)                 // P1 buffer: 8704 floats
#define KTILE3    (128 * 34)                 // P3 buffer: 4352 floats
#define SL_OFF    (KB_OFF + 2 * KTILE)       // 50800
#define OL_OFF    (SL_OFF + 16 * 17)         // 51072
#define ATTN_FLOATS (OL_OFF + 16 * 33)       // 51600
#define ATTN_SMEM (ATTN_FLOATS * 4)          // 206400 bytes

__global__ __launch_bounds__(256) void attn_global_kernel(float* __restrict__ out_w) {
    extern __shared__ float sm[];
    float* S    = sm;
    float* qs   = sm + QS_OFF;     // qs[i] stride 34, scale folded
    float* rinv = sm + RINV_OFF;
    float* kb   = sm + KB_OFF;     // buffers
    float* red  = sm + KB_OFF;     // alias: red[kg][514], kg<32
    float* vl   = sm + KB_OFF;     // alias: local V window 16x33
    float* sl   = sm + SL_OFF;
    float* ol   = sm + OL_OFF;

    const int t  = threadIdx.x;
    const int bh = blockIdx.y;
    const int i0 = blockIdx.x * 16;
    const float* Q = g_qkv + (long long)bh * NNN * DHH;
    const float* K = g_qkv + ((long long)BB * HHH + bh) * NNN * DHH;
    const float* V = g_qkv + ((long long)2 * BB * HHH + bh) * NNN * DHH;

    const int plc = t >> 3, plf = t & 7;     // tile loader coords (c, f4)

    // ---- packed q (pairs over d, scale folded) ----
    {
        int r = t >> 4, d2 = t & 15;
        float2 qv = *(const float2*)(Q + (long long)(i0 + r) * DHH + 2 * d2);
        *(float2*)(qs + r * 34 + 2 * d2) = make_float2(qv.x * SCALE, qv.y * SCALE);
    }

    // ---------- Phase 1: S = q.K^T  (8 tiles of 256 cols, pipelined) ----------
    {
        float4 pk[8];
#define P1_LDG(N) { long long base = (long long)(N) * 256 * DHH;                \
        _Pragma("unroll")                                                       \
        for (int r = 0; r < 8; r++)                                             \
            pk[r] = *(const float4*)(K + base + (long long)(plc + r * 32) * DHH + plf * 4); }
#define P1_STS(BUF) { float* bp = kb + (BUF) * KTILE;                            \
        _Pragma("unroll")                                                        \
        for (int r = 0; r < 8; r++) {                                            \
            float* p = bp + (plc + r * 32) * 34 + plf * 4;                       \
            *(float2*)(p)     = make_float2(pk[r].x, pk[r].y);                   \
            *(float2*)(p + 2) = make_float2(pk[r].z, pk[r].w); } }

        const int cg = t & 63, rg = t >> 6;   // 4 rows x 4 cols / thread
        P1_LDG(0); P1_STS(0); P1_LDG(1);
        __syncthreads();
        for (int n = 0; n < 8; n++) {
            const float* bp = kb + (n & 1) * KTILE;
            const int kj0 = n * 256;
            u64 acc2[4][4] = {};
            #pragma unroll
            for (int d2 = 0; d2 < 16; d2++) {
                u64 k2[4];
                #pragma unroll
                for (int c = 0; c < 4; c++)
                    k2[c] = *(const u64*)(bp + (cg + 64 * c) * 34 + 2 * d2);
                #pragma unroll
                for (int r = 0; r < 4; r++) {
                    u64 q2 = *(const u64*)(qs + (rg * 4 + r) * 34 + 2 * d2);  // bcast
                    #pragma unroll
                    for (int c = 0; c < 4; c++)
                        acc2[r][c] = fma2(q2, k2[c], acc2[r][c]);
                }
            }
            #pragma unroll
            for (int r = 0; r < 4; r++)
                #pragma unroll
                for (int c = 0; c < 4; c++)
                    S[(rg * 4 + r) * SS + kj0 + cg + 64 * c] = pairsum(acc2[r][c]);
            if (n < 7) P1_STS((n + 1) & 1);
            if (n < 6) P1_LDG(n + 2);
            __syncthreads();
        }
    }

    // ---------- Local window attention (block == window), raw S subtile ----------
    {
        #pragma unroll
        for (int r = 0; r < 2; r++) {
            int idx = t + r * 256;
            int i = idx >> 5, d = idx & 31;
            vl[i * 33 + d] = V[(long long)(i0 + i) * DHH + d];
        }
        {
            int row = t >> 4, j = t & 15;
            float s = S[row * SS + i0 + j];
            float m = s;
            #pragma unroll
            for (int o = 8; o; o >>= 1) m = fmaxf(m, __shfl_xor_sync(0xffffffffu, m, o, 16));
            float e = __expf(s - m);
            float ssum = e;
            #pragma unroll
            for (int o = 8; o; o >>= 1) ssum += __shfl_xor_sync(0xffffffffu, ssum, o, 16);
            sl[row * 17 + j] = e / ssum;
        }
        __syncthreads();
        #pragma unroll
        for (int r = 0; r < 2; r++) {
            int idx = t + r * 256;
            int row = idx >> 5, d = idx & 31;
            float a = 0.f;
            #pragma unroll
            for (int j = 0; j < 16; j++) a += sl[row * 17 + j] * vl[j * 33 + d];
            ol[row * 33 + d] = a;
        }
    }
    __syncthreads();

    // ---------- Phase 2: softmax stats (16 lanes/row); S := e ----------
    {
        int row = t >> 4, lane = t & 15;
        float* Sr = S + row * SS;
        float m = -1e30f;
        #pragma unroll 8
        for (int i = 0; i < 32; i++) {
            float4 v = *(const float4*)(Sr + i * 64 + lane * 4);
            m = fmaxf(m, fmaxf(fmaxf(v.x, v.y), fmaxf(v.z, v.w)));
        }
        #pragma unroll
        for (int o = 8; o; o >>= 1) m = fmaxf(m, __shfl_xor_sync(0xffffffffu, m, o, 16));
        float ssum = 0.f;
        #pragma unroll 8
        for (int i = 0; i < 32; i++) {
            float4 v = *(float4*)(Sr + i * 64 + lane * 4);
            v.x = __expf(v.x - m); v.y = __expf(v.y - m);
            v.z = __expf(v.z - m); v.w = __expf(v.w - m);
            *(float4*)(Sr + i * 64 + lane * 4) = v;
            ssum += (v.x + v.y) + (v.z + v.w);
        }
        #pragma unroll
        for (int o = 8; o; o >>= 1) ssum += __shfl_xor_sync(0xffffffffu, ssum, o, 16);
        if (lane == 0) rinv[row] = 1.0f / ssum;
    }
    __syncthreads();

    // ---------- Phase 3: weights write + O = e.V  (16 tiles of 128 rows) ----------
    {
        float4 pv[4];
#define P3_LDG(N) { long long base = (long long)(N) * 128 * DHH;                \
        _Pragma("unroll")                                                       \
        for (int r = 0; r < 4; r++)                                             \
            pv[r] = *(const float4*)(V + base + (long long)(plc + r * 32) * DHH + plf * 4); }
#define P3_STS(BUF) { float* bp = kb + (BUF) * KTILE3;                           \
        _Pragma("unroll")                                                        \
        for (int r = 0; r < 4; r++) {                                            \
            float* p = bp + (plc + r * 32) * 34 + plf * 4;                       \
            *(float2*)(p)     = make_float2(pv[r].x, pv[r].y);                   \
            *(float2*)(p + 2) = make_float2(pv[r].z, pv[r].w); } }

        const int kg = t & 31;           // split-k 32
        const int dg = (t >> 5) & 3;     // 8 dims (4 pairs)
        const int rg = t >> 7;           // 2 groups of 8 rows
        u64 acc2[8][4] = {};
        float* wbase = out_w + (long long)bh * NNN * NNN + (long long)i0 * NNN;

        P3_LDG(0); P3_STS(0); P3_LDG(1);
        __syncthreads();
        for (int n = 0; n < 16; n++) {
            const float* vb = kb + (n & 1) * KTILE3;
            const int vj0 = n * 128;

            #pragma unroll
            for (int i = 0; i < 4; i++) {
                int kl = i * 32 + kg;
                u64 v2[4];
                #pragma unroll
                for (int c = 0; c < 4; c++)
                    v2[c] = *(const u64*)(vb + kl * 34 + dg * 8 + 2 * c);
                #pragma unroll
                for (int rr = 0; rr < 8; rr++) {
                    float s = S[(rg * 8 + rr) * SS + vj0 + kl];
                    u64 sp = pack2(s, s);
                    #pragma unroll
                    for (int c = 0; c < 4; c++)
                        acc2[rr][c] = fma2(sp, v2[c], acc2[rr][c]);
                }
            }

            // write normalized weights for this 128-col chunk (STG drains async)
            #pragma unroll
            for (int s2 = 0; s2 < 2; s2++) {
                int idx = t + s2 * 256;
                int row = idx >> 5, colq = idx & 31;
                float inv = rinv[row];
                float4 v = *(const float4*)(S + row * SS + vj0 + colq * 4);
                v.x *= inv; v.y *= inv; v.z *= inv; v.w *= inv;
                *(float4*)(wbase + (long long)row * NNN + vj0 + colq * 4) = v;
            }

            if (n < 15) P3_STS((n + 1) & 1);
            if (n < 14) P3_LDG(n + 2);
            __syncthreads();
        }

        // buffers dead; region becomes red[]
        #pragma unroll
        for (int rr = 0; rr < 8; rr++)
            #pragma unroll
            for (int c = 0; c < 4; c++)
                *(u64*)(red + kg * 514 + (rg * 8 + rr) * 32 + dg * 8 + 2 * c) = acc2[rr][c];
        __syncthreads();

        const int b = bh >> 3, h = bh & 7;
        #pragma unroll
        for (int s2 = 0; s2 < 2; s2++) {
            int out = t + s2 * 256;
            int row = out >> 5, d = out & 31;
            float sum = 0.f;
            #pragma unroll
            for (int k2 = 0; k2 < 32; k2++) sum += red[k2 * 514 + row * 32 + d];
            sum = sum * rinv[row] + ol[row * 33 + d];
            g_comb[((long long)b * NNN + i0 + row) * CCC + h * DHH + d] = sum;
        }
    }
}

// ============================================================
// Kernel 4: output projection. 128x128 tile, f32x2, pipelined, 2 CTA/SM.
// ============================================================
__global__ __launch_bounds__(256, 2) void proj_gemm_kernel(const float* __restrict__ W,
                                                           const float* __restrict__ bias,
                                                           float* __restrict__ out) {
    __shared__ float Xs[2][16 * 132];
    __shared__ float Ws[2][16 * 128];
    const int t  = threadIdx.x;
    const int tx = t & 15, ty = t >> 4;
    const int m0 = blockIdx.y * 128;
    const int n0 = blockIdx.x * 128;

    u64 acc2[8][4] = {};
    float4 px[2], pw[2];
    const int lm = t >> 2, lc = t & 3;
    const int lk = t >> 5, lnq = t & 31;

#define PROJ_LDG(K0) {                                                                  \
        px[0] = *(const float4*)(g_comb + (long long)(m0 + lm) * CCC + (K0) + 4 * lc);  \
        px[1] = *(const float4*)(g_comb + (long long)(m0 + lm + 64) * CCC + (K0) + 4 * lc); \
        pw[0] = *(const float4*)(W + (long long)((K0) + lk) * CCC + n0 + 4 * lnq);      \
        pw[1] = *(const float4*)(W + (long long)((K0) + lk + 8) * CCC + n0 + 4 * lnq); }
#define PROJ_STS(BUF) {                                                  \
        float* xp = Xs[BUF]; float* wp = Ws[BUF];                        \
        xp[(4 * lc + 0) * 132 + lm] = px[0].x;                           \
        xp[(4 * lc + 1) * 132 + lm] = px[0].y;                           \
        xp[(4 * lc + 2) * 132 + lm] = px[0].z;                           \
        xp[(4 * lc + 3) * 132 + lm] = px[0].w;                           \
        xp[(4 * lc + 0) * 132 + lm + 64] = px[1].x;                      \
        xp[(4 * lc + 1) * 132 + lm + 64] = px[1].y;                      \
        xp[(4 * lc + 2) * 132 + lm + 64] = px[1].z;                      \
        xp[(4 * lc + 3) * 132 + lm + 64] = px[1].w;                      \
        *(float4*)(wp + lk * 128 + 4 * lnq) = pw[0];                     \
        *(float4*)(wp + (lk + 8) * 128 + 4 * lnq) = pw[1]; }

    PROJ_LDG(0); PROJ_STS(0); PROJ_LDG(16);
    __syncthreads();

    for (int kt = 0; kt < 16; kt++) {
        const float* xp = Xs[kt & 1];
        const float* wp = Ws[kt & 1];
        #pragma unroll
        for (int kk = 0; kk < 16; kk++) {
            float4 aa = *(const float4*)(xp + kk * 132 + ty * 8);
            float4 ab = *(const float4*)(xp + kk * 132 + ty * 8 + 4);
            u64 bp[4];
            #pragma unroll
            for (int c = 0; c < 4; c++)
                bp[c] = *(const u64*)(wp + kk * 128 + tx * 2 + 32 * c);
            float av[8] = {aa.x, aa.y, aa.z, aa.w, ab.x, ab.y, ab.z, ab.w};
            #pragma unroll
            for (int r = 0; r < 8; r++) {
                u64 ap = pack2(av[r], av[r]);
                #pragma unroll
                for (int c = 0; c < 4; c++)
                    acc2[r][c] = fma2(ap, bp[c], acc2[r][c]);
            }
        }
        if (kt < 15) PROJ_STS((kt + 1) & 1);
        if (kt < 14) PROJ_LDG((kt + 2) * 16);
        __syncthreads();
    }
    #pragma unroll
    for (int r = 0; r < 8; r++) {
        int row = m0 + ty * 8 + r;
        #pragma unroll
        for (int c = 0; c < 4; c++) {
            int col = n0 + tx * 2 + 32 * c;
            float lo, hi;
            unpack2(acc2[r][c], lo, hi);
            *(float2*)(out + (long long)row * CCC + col) =
                make_float2(lo + bias[col], hi + bias[col + 1]);
        }
    }
}

// ============================================================
extern "C" void kernel_launch(void* const* d_in, const int* in_sizes, int n_in,
                              void* d_out, int out_size) {
    const float* x     = (const float*)d_in[0];
    const float* Wqkv  = (const float*)d_in[1];
    const float* Wproj = (const float*)d_in[2];
    const float* bproj = (const float*)d_in[3];
    float* out   = (float*)d_out;
    float* out_w = out + (long long)BB * NNN * CCC;

    cudaFuncSetAttribute(attn_global_kernel,
                         cudaFuncAttributeMaxDynamicSharedMemorySize, ATTN_SMEM);

    qkv_gemm_kernel<<<dim3(6, 64), 256>>>(x, Wqkv);
    attn_global_kernel<<<dim3(NNN / 16, BB * HHH), 256, ATTN_SMEM>>>(out_w);
    proj_gemm_kernel<<<dim3(2, 64), 256>>>(Wproj, bproj, out);
}

// round 14
// speedup vs baseline: 1.3084x; 1.0099x over previous
#include <cuda_runtime.h>

#define BB   4
#define NNN  2048
#define CCC  256
#define HHH  8
#define DHH  32
#define WINW 16
#define SCALE 0.17677669529663687f   // 32^-0.5

typedef unsigned long long u64;

__device__ __forceinline__ u64 fma2(u64 a, u64 b, u64 c) {
    u64 d;
    asm("fma.rn.f32x2 %0, %1, %2, %3;" : "=l"(d) : "l"(a), "l"(b), "l"(c));
    return d;
}
__device__ __forceinline__ u64 pack2(float lo, float hi) {
    u64 d;
    asm("mov.b64 %0, {%1, %2};" : "=l"(d) : "f"(lo), "f"(hi));
    return d;
}
__device__ __forceinline__ float pairsum(u64 p) {
    float lo, hi;
    asm("mov.b64 {%0, %1}, %2;" : "=f"(lo), "=f"(hi) : "l"(p));
    return lo + hi;
}
__device__ __forceinline__ void unpack2(u64 p, float& lo, float& hi) {
    asm("mov.b64 {%0, %1}, %2;" : "=f"(lo), "=f"(hi) : "l"(p));
}

// -------- scratch (device globals; no allocations allowed) --------
__device__ float g_qkv[3LL * BB * HHH * NNN * DHH];   // [3][B][H][N][32]
__device__ float g_comb[(long long)BB * NNN * CCC];   // [B][N][C]

// ============================================================
// Kernel 1: QKV GEMM.  X[8192,256] @ W[256,768] -> scatter to g_qkv
// 128x128 tile, 256 threads, 8x8 microtile, pipelined, 2 CTA/SM.  (R13 proven)
// ============================================================
__global__ __launch_bounds__(256, 2) void qkv_gemm_kernel(const float* __restrict__ X,
                                                          const float* __restrict__ W) {
    __shared__ float Xs[2][16 * 132];   // Xs[k][m]
    __shared__ float Ws[2][16 * 128];   // Ws[k][n]
    const int t  = threadIdx.x;
    const int tx = t & 15, ty = t >> 4;
    const int m0 = blockIdx.y * 128;
    const int n0 = blockIdx.x * 128;

    u64 acc2[8][4] = {};
    float4 px[2], pw[2];

    const int lm = t >> 2, lc = t & 3;          // X loader coords
    const int lk = t >> 5, lnq = t & 31;        // W loader coords

#define QKV_LDG(K0) {                                                              \
        px[0] = *(const float4*)(X + (long long)(m0 + lm) * CCC + (K0) + 4 * lc);  \
        px[1] = *(const float4*)(X + (long long)(m0 + lm + 64) * CCC + (K0) + 4 * lc); \
        pw[0] = *(const float4*)(W + (long long)((K0) + lk) * 768 + n0 + 4 * lnq); \
        pw[1] = *(const float4*)(W + (long long)((K0) + lk + 8) * 768 + n0 + 4 * lnq); }
#define QKV_STS(BUF) {                                                   \
        float* xp = Xs[BUF]; float* wp = Ws[BUF];                        \
        xp[(4 * lc + 0) * 132 + lm] = px[0].x;                           \
        xp[(4 * lc + 1) * 132 + lm] = px[0].y;                           \
        xp[(4 * lc + 2) * 132 + lm] = px[0].z;                           \
        xp[(4 * lc + 3) * 132 + lm] = px[0].w;                           \
        xp[(4 * lc + 0) * 132 + lm + 64] = px[1].x;                      \
        xp[(4 * lc + 1) * 132 + lm + 64] = px[1].y;                      \
        xp[(4 * lc + 2) * 132 + lm + 64] = px[1].z;                      \
        xp[(4 * lc + 3) * 132 + lm + 64] = px[1].w;                      \
        *(float4*)(wp + lk * 128 + 4 * lnq) = pw[0];                     \
        *(float4*)(wp + (lk + 8) * 128 + 4 * lnq) = pw[1]; }

    QKV_LDG(0); QKV_STS(0); QKV_LDG(16);
    __syncthreads();

    for (int kt = 0; kt < 16; kt++) {
        const float* xp = Xs[kt & 1];
        const float* wp = Ws[kt & 1];
        #pragma unroll
        for (int kk = 0; kk < 16; kk++) {
            float4 aa = *(const float4*)(xp + kk * 132 + ty * 8);
            float4 ab = *(const float4*)(xp + kk * 132 + ty * 8 + 4);
            u64 bp[4];
            #pragma unroll
            for (int c = 0; c < 4; c++)
                bp[c] = *(const u64*)(wp + kk * 128 + tx * 2 + 32 * c);
            float av[8] = {aa.x, aa.y, aa.z, aa.w, ab.x, ab.y, ab.z, ab.w};
            #pragma unroll
            for (int r = 0; r < 8; r++) {
                u64 ap = pack2(av[r], av[r]);
                #pragma unroll
                for (int c = 0; c < 4; c++)
                    acc2[r][c] = fma2(ap, bp[c], acc2[r][c]);
            }
        }
        if (kt < 15) QKV_STS((kt + 1) & 1);
        if (kt < 14) QKV_LDG((kt + 2) * 16);
        __syncthreads();
    }
    #pragma unroll
    for (int r = 0; r < 8; r++) {
        int row = m0 + ty * 8 + r;
        int b   = row >> 11;
        int n   = row & 2047;
        #pragma unroll
        for (int c = 0; c < 4; c++) {
            float lo, hi;
            unpack2(acc2[r][c], lo, hi);
            int col = n0 + tx * 2 + 32 * c;
            #pragma unroll
            for (int j = 0; j < 2; j++) {
                int cc  = col + j;
                int t3  = cc >> 8;
                int rem = cc & 255;
                int h   = rem >> 5;
                int d   = rem & 31;
                g_qkv[((((long long)t3 * BB + b) * HHH + h) * NNN + n) * DHH + d] =
                    (j == 0) ? lo : hi;
            }
        }
    }
}

// ============================================================
// Kernel 2: fused global + local attention per (b,h, 16-row block)
// 256 threads. P1: 256-row K tiles at stride 36, LDS.128 d-pairs,
// row max tracked in registers. P3: 128-row V tiles (stride 34, R13 proven).
// ============================================================
#define SS        2052
#define QS_OFF    (16 * SS)                  // 32832, q stride 36
#define RINV_OFF  (QS_OFF + 16 * 36)         // 33408
#define MXP_OFF   (RINV_OFF + 16)            // 33424  (8 warps x stride 5)
#define KB_OFF    (MXP_OFF + 40)             // 33464  (16B aligned)
#define KT36      (256 * 36)                 // P1 buffer: 9216 floats
#define KTILE3    (128 * 34)                 // P3 buffer: 4352 floats
#define SL_OFF    (KB_OFF + 2 * KT36)        // 51896
#define OL_OFF    (SL_OFF + 16 * 17)         // 52168
#define ATTN_FLOATS (OL_OFF + 16 * 33)       // 52696
#define ATTN_SMEM (ATTN_FLOATS * 4)          // 210784 bytes

__global__ __launch_bounds__(256) void attn_global_kernel(float* __restrict__ out_w) {
    extern __shared__ float sm[];
    float* S    = sm;
    float* qs   = sm + QS_OFF;     // qs[i] stride 36, scale folded
    float* rinv = sm + RINV_OFF;
    float* mxp  = sm + MXP_OFF;    // per-warp row maxima
    float* kb   = sm + KB_OFF;     // buffers
    float* red  = sm + KB_OFF;     // alias: red[kg][514], kg<32 (16448 fl <= 18432)
    float* vl   = sm + KB_OFF;     // alias: local V window 16x33
    float* sl   = sm + SL_OFF;
    float* ol   = sm + OL_OFF;

    const int t  = threadIdx.x;
    const int bh = blockIdx.y;
    const int i0 = blockIdx.x * 16;
    const float* Q = g_qkv + (long long)bh * NNN * DHH;
    const float* K = g_qkv + ((long long)BB * HHH + bh) * NNN * DHH;
    const float* V = g_qkv + ((long long)2 * BB * HHH + bh) * NNN * DHH;

    const int plc = t >> 3, plf = t & 7;     // tile loader coords (c, f4)

    // ---- packed q (pairs over d, scale folded), stride 36 ----
    {
        int r = t >> 4, d2 = t & 15;
        float2 qv = *(const float2*)(Q + (long long)(i0 + r) * DHH + 2 * d2);
        *(float2*)(qs + r * 36 + 2 * d2) = make_float2(qv.x * SCALE, qv.y * SCALE);
    }

    // ---------- Phase 1: S = q.K^T  (8 tiles of 256 cols, pipelined) ----------
    {
        float4 pk[8];
#define P1_LDG(N) { long long base = (long long)(N) * 256 * DHH;                \
        _Pragma("unroll")                                                       \
        for (int r = 0; r < 8; r++)                                             \
            pk[r] = *(const float4*)(K + base + (long long)(plc + r * 32) * DHH + plf * 4); }
#define P1_STS(BUF) { float* bp = kb + (BUF) * KT36;                             \
        _Pragma("unroll")                                                        \
        for (int r = 0; r < 8; r++)                                              \
            *(float4*)(bp + (plc + r * 32) * 36 + plf * 4) = pk[r]; }

        const int cg = t & 63, rg = t >> 6;   // 4 rows x 4 cols / thread
        float mx4[4] = {-1e30f, -1e30f, -1e30f, -1e30f};
        P1_LDG(0); P1_STS(0); P1_LDG(1);
        __syncthreads();
        for (int n = 0; n < 8; n++) {
            const float* bp = kb + (n & 1) * KT36;
            const int kj0 = n * 256;
            u64 acc2[4][4] = {};
            #pragma unroll
            for (int p = 0; p < 8; p++) {         // d-pair steps: dims 4p..4p+3
                u64 k2[4][2];
                #pragma unroll
                for (int c = 0; c < 4; c++) {
                    float4 kv = *(const float4*)(bp + (cg + 64 * c) * 36 + 4 * p);
                    k2[c][0] = pack2(kv.x, kv.y);
                    k2[c][1] = pack2(kv.z, kv.w);
                }
                #pragma unroll
                for (int r = 0; r < 4; r++) {
                    float4 qv = *(const float4*)(qs + (rg * 4 + r) * 36 + 4 * p); // bcast
                    u64 qa = pack2(qv.x, qv.y);
                    u64 qb = pack2(qv.z, qv.w);
                    #pragma unroll
                    for (int c = 0; c < 4; c++) {
                        acc2[r][c] = fma2(qa, k2[c][0], acc2[r][c]);
                        acc2[r][c] = fma2(qb, k2[c][1], acc2[r][c]);
                    }
                }
            }
            #pragma unroll
            for (int r = 0; r < 4; r++)
                #pragma unroll
                for (int c = 0; c < 4; c++) {
                    float s = pairsum(acc2[r][c]);
                    S[(rg * 4 + r) * SS + kj0 + cg + 64 * c] = s;
                    mx4[r] = fmaxf(mx4[r], s);
                }
            if (n < 7) P1_STS((n + 1) & 1);
            if (n < 6) P1_LDG(n + 2);
            __syncthreads();
        }
        // warp-reduce row maxima (all lanes in a warp share the same 4 rows)
        #pragma unroll
        for (int r = 0; r < 4; r++) {
            #pragma unroll
            for (int o = 16; o; o >>= 1)
                mx4[r] = fmaxf(mx4[r], __shfl_xor_sync(0xffffffffu, mx4[r], o));
        }
        if ((t & 31) == 0) {
            #pragma unroll
            for (int r = 0; r < 4; r++) mxp[(t >> 5) * 5 + r] = mx4[r];
        }
    }

    // ---------- Local window attention (block == window), raw S subtile ----------
    {
        #pragma unroll
        for (int r = 0; r < 2; r++) {
            int idx = t + r * 256;
            int i = idx >> 5, d = idx & 31;
            vl[i * 33 + d] = V[(long long)(i0 + i) * DHH + d];
        }
        {
            int row = t >> 4, j = t & 15;
            float s = S[row * SS + i0 + j];
            float m = s;
            #pragma unroll
            for (int o = 8; o; o >>= 1) m = fmaxf(m, __shfl_xor_sync(0xffffffffu, m, o, 16));
            float e = __expf(s - m);
            float ssum = e;
            #pragma unroll
            for (int o = 8; o; o >>= 1) ssum += __shfl_xor_sync(0xffffffffu, ssum, o, 16);
            sl[row * 17 + j] = e / ssum;
        }
        __syncthreads();
        #pragma unroll
        for (int r = 0; r < 2; r++) {
            int idx = t + r * 256;
            int row = idx >> 5, d = idx & 31;
            float a = 0.f;
            #pragma unroll
            for (int j = 0; j < 16; j++) a += sl[row * 17 + j] * vl[j * 33 + d];
            ol[row * 33 + d] = a;
        }
    }
    __syncthreads();

    // ---------- Phase 2: exp pass only (max from mxp); S := e ----------
    {
        int row = t >> 4, lane = t & 15;
        int rg = row >> 2, rr = row & 3;
        float m = fmaxf(mxp[rg * 10 + rr], mxp[rg * 10 + 5 + rr]);
        float* Sr = S + row * SS;
        float ssum = 0.f;
        #pragma unroll 8
        for (int i = 0; i < 32; i++) {
            float4 v = *(float4*)(Sr + i * 64 + lane * 4);
            v.x = __expf(v.x - m); v.y = __expf(v.y - m);
            v.z = __expf(v.z - m); v.w = __expf(v.w - m);
            *(float4*)(Sr + i * 64 + lane * 4) = v;
            ssum += (v.x + v.y) + (v.z + v.w);
        }
        #pragma unroll
        for (int o = 8; o; o >>= 1) ssum += __shfl_xor_sync(0xffffffffu, ssum, o, 16);
        if (lane == 0) rinv[row] = 1.0f / ssum;
    }
    __syncthreads();

    // ---------- Phase 3: weights write + O = e.V  (16 tiles of 128 rows) ----------
    {
        float4 pv[4];
#define P3_LDG(N) { long long base = (long long)(N) * 128 * DHH;                \
        _Pragma("unroll")                                                       \
        for (int r = 0; r < 4; r++)                                             \
            pv[r] = *(const float4*)(V + base + (long long)(plc + r * 32) * DHH + plf * 4); }
#define P3_STS(BUF) { float* bp = kb + (BUF) * KTILE3;                           \
        _Pragma("unroll")                                                        \
        for (int r = 0; r < 4; r++) {                                            \
            float* p = bp + (plc + r * 32) * 34 + plf * 4;                       \
            *(float2*)(p)     = make_float2(pv[r].x, pv[r].y);                   \
            *(float2*)(p + 2) = make_float2(pv[r].z, pv[r].w); } }

        const int kg = t & 31;           // split-k 32
        const int dg = (t >> 5) & 3;     // 8 dims (4 pairs)
        const int rg = t >> 7;           // 2 groups of 8 rows
        u64 acc2[8][4] = {};
        float* wbase = out_w + (long long)bh * NNN * NNN + (long long)i0 * NNN;

        P3_LDG(0); P3_STS(0); P3_LDG(1);
        __syncthreads();
        for (int n = 0; n < 16; n++) {
            const float* vb = kb + (n & 1) * KTILE3;
            const int vj0 = n * 128;

            #pragma unroll
            for (int i = 0; i < 4; i++) {
                int kl = i * 32 + kg;
                u64 v2[4];
                #pragma unroll
                for (int c = 0; c < 4; c++)
                    v2[c] = *(const u64*)(vb + kl * 34 + dg * 8 + 2 * c);
                #pragma unroll
                for (int rr = 0; rr < 8; rr++) {
                    float s = S[(rg * 8 + rr) * SS + vj0 + kl];
                    u64 sp = pack2(s, s);
                    #pragma unroll
                    for (int c = 0; c < 4; c++)
                        acc2[rr][c] = fma2(sp, v2[c], acc2[rr][c]);
                }
            }

            // write normalized weights for this 128-col chunk (STG drains async)
            #pragma unroll
            for (int s2 = 0; s2 < 2; s2++) {
                int idx = t + s2 * 256;
                int row = idx >> 5, colq = idx & 31;
                float inv = rinv[row];
                float4 v = *(const float4*)(S + row * SS + vj0 + colq * 4);
                v.x *= inv; v.y *= inv; v.z *= inv; v.w *= inv;
                *(float4*)(wbase + (long long)row * NNN + vj0 + colq * 4) = v;
            }

            if (n < 15) P3_STS((n + 1) & 1);
            if (n < 14) P3_LDG(n + 2);
            __syncthreads();
        }

        // buffers dead; region becomes red[]
        #pragma unroll
        for (int rr = 0; rr < 8; rr++)
            #pragma unroll
            for (int c = 0; c < 4; c++)
                *(u64*)(red + kg * 514 + (rg * 8 + rr) * 32 + dg * 8 + 2 * c) = acc2[rr][c];
        __syncthreads();

        const int b = bh >> 3, h = bh & 7;
        #pragma unroll
        for (int s2 = 0; s2 < 2; s2++) {
            int out = t + s2 * 256;
            int row = out >> 5, d = out & 31;
            float sum = 0.f;
            #pragma unroll
            for (int k2 = 0; k2 < 32; k2++) sum += red[k2 * 514 + row * 32 + d];
            sum = sum * rinv[row] + ol[row * 33 + d];
            g_comb[((long long)b * NNN + i0 + row) * CCC + h * DHH + d] = sum;
        }
    }
}

// ============================================================
// Kernel 4: output projection. 128x128 tile, f32x2, pipelined, 2 CTA/SM.
// ============================================================
__global__ __launch_bounds__(256, 2) void proj_gemm_kernel(const float* __restrict__ W,
                                                           const float* __restrict__ bias,
                                                           float* __restrict__ out) {
    __shared__ float Xs[2][16 * 132];
    __shared__ float Ws[2][16 * 128];
    const int t  = threadIdx.x;
    const int tx = t & 15, ty = t >> 4;
    const int m0 = blockIdx.y * 128;
    const int n0 = blockIdx.x * 128;

    u64 acc2[8][4] = {};
    float4 px[2], pw[2];
    const int lm = t >> 2, lc = t & 3;
    const int lk = t >> 5, lnq = t & 31;

#define PROJ_LDG(K0) {                                                                  \
        px[0] = *(const float4*)(g_comb + (long long)(m0 + lm) * CCC + (K0) + 4 * lc);  \
        px[1] = *(const float4*)(g_comb + (long long)(m0 + lm + 64) * CCC + (K0) + 4 * lc); \
        pw[0] = *(const float4*)(W + (long long)((K0) + lk) * CCC + n0 + 4 * lnq);      \
        pw[1] = *(const float4*)(W + (long long)((K0) + lk + 8) * CCC + n0 + 4 * lnq); }
#define PROJ_STS(BUF) {                                                  \
        float* xp = Xs[BUF]; float* wp = Ws[BUF];                        \
        xp[(4 * lc + 0) * 132 + lm] = px[0].x;                           \
        xp[(4 * lc + 1) * 132 + lm] = px[0].y;                           \
        xp[(4 * lc + 2) * 132 + lm] = px[0].z;                           \
        xp[(4 * lc + 3) * 132 + lm] = px[0].w;                           \
        xp[(4 * lc + 0) * 132 + lm + 64] = px[1].x;                      \
        xp[(4 * lc + 1) * 132 + lm + 64] = px[1].y;                      \
        xp[(4 * lc + 2) * 132 + lm + 64] = px[1].z;                      \
        xp[(4 * lc + 3) * 132 + lm + 64] = px[1].w;                      \
        *(float4*)(wp + lk * 128 + 4 * lnq) = pw[0];                     \
        *(float4*)(wp + (lk + 8) * 128 + 4 * lnq) = pw[1]; }

    PROJ_LDG(0); PROJ_STS(0); PROJ_LDG(16);
    __syncthreads();

    for (int kt = 0; kt < 16; kt++) {
        const float* xp = Xs[kt & 1];
        const float* wp = Ws[kt & 1];
        #pragma unroll
        for (int kk = 0; kk < 16; kk++) {
            float4 aa = *(const float4*)(xp + kk * 132 + ty * 8);
            float4 ab = *(const float4*)(xp + kk * 132 + ty * 8 + 4);
            u64 bp[4];
            #pragma unroll
            for (int c = 0; c < 4; c++)
                bp[c] = *(const u64*)(wp + kk * 128 + tx * 2 + 32 * c);
            float av[8] = {aa.x, aa.y, aa.z, aa.w, ab.x, ab.y, ab.z, ab.w};
            #pragma unroll
            for (int r = 0; r < 8; r++) {
                u64 ap = pack2(av[r], av[r]);
                #pragma unroll
                for (int c = 0; c < 4; c++)
                    acc2[r][c] = fma2(ap, bp[c], acc2[r][c]);
            }
        }
        if (kt < 15) PROJ_STS((kt + 1) & 1);
        if (kt < 14) PROJ_LDG((kt + 2) * 16);
        __syncthreads();
    }
    #pragma unroll
    for (int r = 0; r < 8; r++) {
        int row = m0 + ty * 8 + r;
        #pragma unroll
        for (int c = 0; c < 4; c++) {
            int col = n0 + tx * 2 + 32 * c;
            float lo, hi;
            unpack2(acc2[r][c], lo, hi);
            *(float2*)(out + (long long)row * CCC + col) =
                make_float2(lo + bias[col], hi + bias[col + 1]);
        }
    }
}

// ============================================================
extern "C" void kernel_launch(void* const* d_in, const int* in_sizes, int n_in,
                              void* d_out, int out_size) {
    const float* x     = (const float*)d_in[0];
    const float* Wqkv  = (const float*)d_in[1];
    const float* Wproj = (const float*)d_in[2];
    const float* bproj = (const float*)d_in[3];
    float* out   = (float*)d_out;
    float* out_w = out + (long long)BB * NNN * CCC;

    cudaFuncSetAttribute(attn_global_kernel,
                         cudaFuncAttributeMaxDynamicSharedMemorySize, ATTN_SMEM);

    qkv_gemm_kernel<<<dim3(6, 64), 256>>>(x, Wqkv);
    attn_global_kernel<<<dim3(NNN / 16, BB * HHH), 256, ATTN_SMEM>>>(out_w);
    proj_gemm_kernel<<<dim3(2, 64), 256>>>(Wproj, bproj, out);
}

// round 17
// speedup vs baseline: 1.3384x; 1.0229x over previous
#include <cuda_runtime.h>
#include <cuda_bf16.h>
#include <cstdint>

#define BB   4
#define NNN  2048
#define CCC  256
#define HHH  8
#define DHH  32
#define SCALE 0.17677669529663687f   // 32^-0.5

typedef unsigned long long u64;

__device__ __forceinline__ u64 fma2(u64 a, u64 b, u64 c) {
    u64 d;
    asm("fma.rn.f32x2 %0, %1, %2, %3;" : "=l"(d) : "l"(a), "l"(b), "l"(c));
    return d;
}
__device__ __forceinline__ u64 pack2(float lo, float hi) {
    u64 d;
    asm("mov.b64 %0, {%1, %2};" : "=l"(d) : "f"(lo), "f"(hi));
    return d;
}
__device__ __forceinline__ void unpack2(u64 p, float& lo, float& hi) {
    asm("mov.b64 {%0, %1}, %2;" : "=f"(lo), "=f"(hi) : "l"(p));
}

// bf16x2 mma (m16n8k16, row.col, f32 accum) — standard sm_80+ PTX
__device__ __forceinline__ void mma16816(float c[4], const uint32_t a[4],
                                         uint32_t b0, uint32_t b1) {
    asm volatile("mma.sync.aligned.m16n8k16.row.col.f32.bf16.bf16.f32 "
        "{%0,%1,%2,%3}, {%4,%5,%6,%7}, {%8,%9}, {%0,%1,%2,%3};"
        : "+f"(c[0]), "+f"(c[1]), "+f"(c[2]), "+f"(c[3])
        : "r"(a[0]), "r"(a[1]), "r"(a[2]), "r"(a[3]), "r"(b0), "r"(b1));
}

#define SPLITP(px, py, HI, LO) {                                             \
    __nv_bfloat16 hx = __float2bfloat16(px), hy = __float2bfloat16(py);      \
    HI = (uint32_t)__bfloat16_as_ushort(hx)                                  \
       | ((uint32_t)__bfloat16_as_ushort(hy) << 16);                         \
    __nv_bfloat16 lx = __float2bfloat16((px) - __bfloat162float(hx));        \
    __nv_bfloat16 ly = __float2bfloat16((py) - __bfloat162float(hy));        \
    LO = (uint32_t)__bfloat16_as_ushort(lx)                                  \
       | ((uint32_t)__bfloat16_as_ushort(ly) << 16); }

// -------- scratch (device globals; no allocations allowed) --------
__device__ float g_qkv[3LL * BB * HHH * NNN * DHH];   // [3][B][H][N][32]
__device__ float g_comb[(long long)BB * NNN * CCC];   // [B][N][C]
__device__ __nv_bfloat16 g_kh[32LL * NNN * DHH];      // K hi [bh][n][d]
__device__ __nv_bfloat16 g_kl[32LL * NNN * DHH];      // K lo

// ============================================================
// Kernel 1: QKV GEMM (R13-proven) + bf16-split K emission
// ============================================================
__global__ __launch_bounds__(256, 2) void qkv_gemm_kernel(const float* __restrict__ X,
                                                          const float* __restrict__ W) {
    __shared__ float Xs[2][16 * 132];
    __shared__ float Ws[2][16 * 128];
    const int t  = threadIdx.x;
    const int tx = t & 15, ty = t >> 4;
    const int m0 = blockIdx.y * 128;
    const int n0 = blockIdx.x * 128;

    u64 acc2[8][4] = {};
    float4 px[2], pw[2];
    const int lm = t >> 2, lc = t & 3;
    const int lk = t >> 5, lnq = t & 31;

#define QKV_LDG(K0) {                                                              \
        px[0] = *(const float4*)(X + (long long)(m0 + lm) * CCC + (K0) + 4 * lc);  \
        px[1] = *(const float4*)(X + (long long)(m0 + lm + 64) * CCC + (K0) + 4 * lc); \
        pw[0] = *(const float4*)(W + (long long)((K0) + lk) * 768 + n0 + 4 * lnq); \
        pw[1] = *(const float4*)(W + (long long)((K0) + lk + 8) * 768 + n0 + 4 * lnq); }
#define QKV_STS(BUF) {                                                   \
        float* xp = Xs[BUF]; float* wp = Ws[BUF];                        \
        xp[(4 * lc + 0) * 132 + lm] = px[0].x;                           \
        xp[(4 * lc + 1) * 132 + lm] = px[0].y;                           \
        xp[(4 * lc + 2) * 132 + lm] = px[0].z;                           \
        xp[(4 * lc + 3) * 132 + lm] = px[0].w;                           \
        xp[(4 * lc + 0) * 132 + lm + 64] = px[1].x;                      \
        xp[(4 * lc + 1) * 132 + lm + 64] = px[1].y;                      \
        xp[(4 * lc + 2) * 132 + lm + 64] = px[1].z;                      \
        xp[(4 * lc + 3) * 132 + lm + 64] = px[1].w;                      \
        *(float4*)(wp + lk * 128 + 4 * lnq) = pw[0];                     \
        *(float4*)(wp + (lk + 8) * 128 + 4 * lnq) = pw[1]; }

    QKV_LDG(0); QKV_STS(0); QKV_LDG(16);
    __syncthreads();

    for (int kt = 0; kt < 16; kt++) {
        const float* xp = Xs[kt & 1];
        const float* wp = Ws[kt & 1];
        #pragma unroll
        for (int kk = 0; kk < 16; kk++) {
            float4 aa = *(const float4*)(xp + kk * 132 + ty * 8);
            float4 ab = *(const float4*)(xp + kk * 132 + ty * 8 + 4);
            u64 bp[4];
            #pragma unroll
            for (int c = 0; c < 4; c++)
                bp[c] = *(const u64*)(wp + kk * 128 + tx * 2 + 32 * c);
            float av[8] = {aa.x, aa.y, aa.z, aa.w, ab.x, ab.y, ab.z, ab.w};
            #pragma unroll
            for (int r = 0; r < 8; r++) {
                u64 ap = pack2(av[r], av[r]);
                #pragma unroll
                for (int c = 0; c < 4; c++)
                    acc2[r][c] = fma2(ap, bp[c], acc2[r][c]);
            }
        }
        if (kt < 15) QKV_STS((kt + 1) & 1);
        if (kt < 14) QKV_LDG((kt + 2) * 16);
        __syncthreads();
    }
    #pragma unroll
    for (int r = 0; r < 8; r++) {
        int row = m0 + ty * 8 + r;
        int b   = row >> 11;
        int n   = row & 2047;
        #pragma unroll
        for (int c = 0; c < 4; c++) {
            float lo, hi;
            unpack2(acc2[r][c], lo, hi);
            int col = n0 + tx * 2 + 32 * c;
            #pragma unroll
            for (int j = 0; j < 2; j++) {
                int cc  = col + j;
                int t3  = cc >> 8;
                int rem = cc & 255;
                int h   = rem >> 5;
                int d   = rem & 31;
                float val = (j == 0) ? lo : hi;
                g_qkv[((((long long)t3 * BB + b) * HHH + h) * NNN + n) * DHH + d] = val;
                if (t3 == 1) {
                    __nv_bfloat16 h16 = __float2bfloat16(val);
                    float rr = val - __bfloat162float(h16);
                    long long o = (((long long)(b * 8 + h)) * NNN + n) * DHH + d;
                    g_kh[o] = h16;
                    g_kl[o] = __float2bfloat16(rr);
                }
            }
        }
    }
}

// ============================================================
// Kernel 2: fused attention per (b,h, 16-row block), 256 threads.
// P1 on HMMA (mma.sync bf16 split). P2/local/P3 as R14 (proven).
// ============================================================
#define SSW       2056                        // S row stride (words); 2056 % 32 == 8
#define SM_S      0                           // 16*2056*4      = 131584
#define SM_QS     131584                      // 16*34*4        = 2176
#define SM_RINV   133760                      // 64
#define SM_MXP    133824                      // 8*16*4         = 512
#define SM_SL     134336                      // 16*17*4        = 1088
#define SM_OL     135424                      // 16*33*4        = 2112
#define SM_KB     137600                      // 2 * (20480+20480) = 81920
#define ATTN_SMEM 219520
#define KBUF_U32  10240                       // u32 per buffer (hi 5120 + lo 5120)
#define KTILE3    (128 * 34)                  // P3 fp32 V buffer (floats)

__global__ __launch_bounds__(256) void attn_global_kernel(float* __restrict__ out_w) {
    extern __shared__ char smc[];
    float* smf = (float*)smc;
    float* S    = smf;                        // [16][2056]
    float* qs   = smf + SM_QS / 4;            // stride 34, SCALE folded
    float* rinv = smf + SM_RINV / 4;
    float* mxp  = smf + SM_MXP / 4;           // [8 warps][16 rows]
    float* sl   = smf + SM_SL / 4;
    float* ol   = smf + SM_OL / 4;
    uint32_t* kbu = (uint32_t*)(smc + SM_KB); // P1 bf16 K tiles
    float* kb3  = smf + SM_KB / 4;            // P3 fp32 V tiles (alias)
    float* red  = smf + SM_KB / 4;            // alias: red[kg][514]
    float* vl   = smf + SM_KB / 4;            // alias: local V window

    const int t = threadIdx.x;
    const int w = t >> 5, lid = t & 31;
    const int g = lid >> 2, tq = lid & 3;
    const int bh = blockIdx.y;
    const int i0 = blockIdx.x * 16;
    const float* Q = g_qkv + (long long)bh * NNN * DHH;
    const float* V = g_qkv + ((long long)2 * BB * HHH + bh) * NNN * DHH;
    const __nv_bfloat16* KH = g_kh + (long long)bh * NNN * DHH;
    const __nv_bfloat16* KL = g_kl + (long long)bh * NNN * DHH;

    // ---- q prologue (fp32, SCALE folded) ----
    {
        int r = t >> 4, d2 = t & 15;
        float2 qv = *(const float2*)(Q + (long long)(i0 + r) * DHH + 2 * d2);
        *(float2*)(qs + r * 34 + 2 * d2) = make_float2(qv.x * SCALE, qv.y * SCALE);
    }

    // ---------- Phase 1: S = q.K^T on HMMA (8 tiles of 256 cols) ----------
    {
        uint4 pkh[4], pkl[4];
#define P1_LDG(N) {                                                             \
        const uint4* sh_ = (const uint4*)(KH + ((long long)(N) * 256 + t) * 32);\
        const uint4* sl_ = (const uint4*)(KL + ((long long)(N) * 256 + t) * 32);\
        pkh[0] = sh_[0]; pkh[1] = sh_[1]; pkh[2] = sh_[2]; pkh[3] = sh_[3];     \
        pkl[0] = sl_[0]; pkl[1] = sl_[1]; pkl[2] = sl_[2]; pkl[3] = sl_[3]; }
#define P1_STS(BUF) {                                                           \
        uint4* dh = (uint4*)(kbu + (BUF) * KBUF_U32 + t * 20);                  \
        uint4* dl = (uint4*)(kbu + (BUF) * KBUF_U32 + 5120 + t * 20);           \
        dh[0] = pkh[0]; dh[1] = pkh[1]; dh[2] = pkh[2]; dh[3] = pkh[3];         \
        dl[0] = pkl[0]; dl[1] = pkl[1]; dl[2] = pkl[2]; dl[3] = pkl[3]; }

        P1_LDG(0); P1_STS(0); P1_LDG(1);
        __syncthreads();

        // A fragments (q split hi/lo, 2 ksteps) — qs visible after the sync
        uint32_t aqh[2][4], aql[2][4];
        #pragma unroll
        for (int k = 0; k < 2; k++)
            #pragma unroll
            for (int j = 0; j < 4; j++) {
                int row = (j & 1) ? g + 8 : g;
                int col = 2 * tq + 16 * k + ((j >> 1) ? 8 : 0);
                float2 v = *(const float2*)(qs + row * 34 + col);
                SPLITP(v.x, v.y, aqh[k][j], aql[k][j]);
            }

        float mxr0 = -1e30f, mxr1 = -1e30f;     // rows g, g+8
        for (int n = 0; n < 8; n++) {
            const uint32_t* khs = kbu + (n & 1) * KBUF_U32;
            const uint32_t* kls = khs + 5120;
            #pragma unroll
            for (int blk = 0; blk < 4; blk++) {
                int lcol = w * 32 + blk * 8 + g;     // col within tile
                int cb   = n * 256 + w * 32 + blk * 8;
                float c[4] = {0.f, 0.f, 0.f, 0.f};
                #pragma unroll
                for (int k = 0; k < 2; k++) {
                    uint32_t bh0 = khs[lcol * 20 + tq + 8 * k];
                    uint32_t bh1 = khs[lcol * 20 + tq + 4 + 8 * k];
                    uint32_t bl0 = kls[lcol * 20 + tq + 8 * k];
                    uint32_t bl1 = kls[lcol * 20 + tq + 4 + 8 * k];
                    mma16816(c, aqh[k], bh0, bh1);
                    mma16816(c, aqh[k], bl0, bl1);
                    mma16816(c, aql[k], bh0, bh1);
                }
                *(float2*)(S + g * SSW + cb + 2 * tq)       = make_float2(c[0], c[1]);
                *(float2*)(S + (g + 8) * SSW + cb + 2 * tq) = make_float2(c[2], c[3]);
                mxr0 = fmaxf(mxr0, fmaxf(c[0], c[1]));
                mxr1 = fmaxf(mxr1, fmaxf(c[2], c[3]));
            }
            if (n < 7) P1_STS((n + 1) & 1);
            if (n < 6) P1_LDG(n + 2);
            __syncthreads();
        }
        // reduce row maxima over the 4 lanes sharing each row
        #pragma unroll
        for (int o = 1; o < 4; o <<= 1) {
            mxr0 = fmaxf(mxr0, __shfl_xor_sync(0xffffffffu, mxr0, o));
            mxr1 = fmaxf(mxr1, __shfl_xor_sync(0xffffffffu, mxr1, o));
        }
        if (tq == 0) {
            mxp[w * 16 + g]     = mxr0;
            mxp[w * 16 + g + 8] = mxr1;
        }
    }

    // ---------- Local window attention (block == window), raw S subtile ----------
    {
        #pragma unroll
        for (int r = 0; r < 2; r++) {
            int idx = t + r * 256;
            int i = idx >> 5, d = idx & 31;
            vl[i * 33 + d] = V[(long long)(i0 + i) * DHH + d];
        }
        {
            int row = t >> 4, j = t & 15;
            float s = S[row * SSW + i0 + j];
            float m = s;
            #pragma unroll
            for (int o = 8; o; o >>= 1) m = fmaxf(m, __shfl_xor_sync(0xffffffffu, m, o, 16));
            float e = __expf(s - m);
            float ssum = e;
            #pragma unroll
            for (int o = 8; o; o >>= 1) ssum += __shfl_xor_sync(0xffffffffu, ssum, o, 16);
            sl[row * 17 + j] = e / ssum;
        }
        __syncthreads();
        #pragma unroll
        for (int r = 0; r < 2; r++) {
            int idx = t + r * 256;
            int row = idx >> 5, d = idx & 31;
            float a = 0.f;
            #pragma unroll
            for (int j = 0; j < 16; j++) a += sl[row * 17 + j] * vl[j * 33 + d];
            ol[row * 33 + d] = a;
        }
    }
    __syncthreads();

    // ---------- Phase 2: exp pass (max from mxp); S := e ----------
    {
        int row = t >> 4, lane = t & 15;
        float m = -1e30f;
        #pragma unroll
        for (int w2 = 0; w2 < 8; w2++) m = fmaxf(m, mxp[w2 * 16 + row]);
        float* Sr = S + row * SSW;
        float ssum = 0.f;
        #pragma unroll 8
        for (int i = 0; i < 32; i++) {
            float4 v = *(float4*)(Sr + i * 64 + lane * 4);
            v.x = __expf(v.x - m); v.y = __expf(v.y - m);
            v.z = __expf(v.z - m); v.w = __expf(v.w - m);
            *(float4*)(Sr + i * 64 + lane * 4) = v;
            ssum += (v.x + v.y) + (v.z + v.w);
        }
        #pragma unroll
        for (int o = 8; o; o >>= 1) ssum += __shfl_xor_sync(0xffffffffu, ssum, o, 16);
        if (lane == 0) rinv[row] = 1.0f / ssum;
    }
    __syncthreads();

    // ---------- Phase 3: weights write + O = e.V  (16 tiles of 128 rows) ----------
    {
        float4 pv[4];
        const int plc = t >> 3, plf = t & 7;
#define P3_LDG(N) { long long base = (long long)(N) * 128 * DHH;                \
        _Pragma("unroll")                                                       \
        for (int r = 0; r < 4; r++)                                             \
            pv[r] = *(const float4*)(V + base + (long long)(plc + r * 32) * DHH + plf * 4); }
#define P3_STS(BUF) { float* bp = kb3 + (BUF) * KTILE3;                          \
        _Pragma("unroll")                                                        \
        for (int r = 0; r < 4; r++) {                                            \
            float* p = bp + (plc + r * 32) * 34 + plf * 4;                       \
            *(float2*)(p)     = make_float2(pv[r].x, pv[r].y);                   \
            *(float2*)(p + 2) = make_float2(pv[r].z, pv[r].w); } }

        const int kg = t & 31;           // split-k 32
        const int dg = (t >> 5) & 3;     // 8 dims (4 pairs)
        const int rg = t >> 7;           // 2 groups of 8 rows
        u64 acc2[8][4] = {};
        float* wbase = out_w + (long long)bh * NNN * NNN + (long long)i0 * NNN;

        P3_LDG(0); P3_STS(0); P3_LDG(1);
        __syncthreads();
        for (int n = 0; n < 16; n++) {
            const float* vb = kb3 + (n & 1) * KTILE3;
            const int vj0 = n * 128;

            #pragma unroll
            for (int i = 0; i < 4; i++) {
                int kl = i * 32 + kg;
                u64 v2[4];
                #pragma unroll
                for (int c = 0; c < 4; c++)
                    v2[c] = *(const u64*)(vb + kl * 34 + dg * 8 + 2 * c);
                #pragma unroll
                for (int rr = 0; rr < 8; rr++) {
                    float s = S[(rg * 8 + rr) * SSW + vj0 + kl];
                    u64 sp = pack2(s, s);
                    #pragma unroll
                    for (int c = 0; c < 4; c++)
                        acc2[rr][c] = fma2(sp, v2[c], acc2[rr][c]);
                }
            }

            // write normalized weights for this 128-col chunk
            #pragma unroll
            for (int s2 = 0; s2 < 2; s2++) {
                int idx = t + s2 * 256;
                int row = idx >> 5, colq = idx & 31;
                float inv = rinv[row];
                float4 v = *(const float4*)(S + row * SSW + vj0 + colq * 4);
                v.x *= inv; v.y *= inv; v.z *= inv; v.w *= inv;
                *(float4*)(wbase + (long long)row * NNN + vj0 + colq * 4) = v;
            }

            if (n < 15) P3_STS((n + 1) & 1);
            if (n < 14) P3_LDG(n + 2);
            __syncthreads();
        }

        // buffers dead; region becomes red[]
        #pragma unroll
        for (int rr = 0; rr < 8; rr++)
            #pragma unroll
            for (int c = 0; c < 4; c++)
                *(u64*)(red + kg * 514 + (rg * 8 + rr) * 32 + dg * 8 + 2 * c) = acc2[rr][c];
        __syncthreads();

        const int b = bh >> 3, h = bh & 7;
        #pragma unroll
        for (int s2 = 0; s2 < 2; s2++) {
            int out = t + s2 * 256;
            int row = out >> 5, d = out & 31;
            float sum = 0.f;
            #pragma unroll
            for (int k2 = 0; k2 < 32; k2++) sum += red[k2 * 514 + row * 32 + d];
            sum = sum * rinv[row] + ol[row * 33 + d];
            g_comb[((long long)b * NNN + i0 + row) * CCC + h * DHH + d] = sum;
        }
    }
}

// ============================================================
// Kernel 4: output projection. (R13 proven)
// ============================================================
__global__ __launch_bounds__(256, 2) void proj_gemm_kernel(const float* __restrict__ W,
                                                           const float* __restrict__ bias,
                                                           float* __restrict__ out) {
    __shared__ float Xs[2][16 * 132];
    __shared__ float Ws[2][16 * 128];
    const int t  = threadIdx.x;
    const int tx = t & 15, ty = t >> 4;
    const int m0 = blockIdx.y * 128;
    const int n0 = blockIdx.x * 128;

    u64 acc2[8][4] = {};
    float4 px[2], pw[2];
    const int lm = t >> 2, lc = t & 3;
    const int lk = t >> 5, lnq = t & 31;

#define PROJ_LDG(K0) {                                                                  \
        px[0] = *(const float4*)(g_comb + (long long)(m0 + lm) * CCC + (K0) + 4 * lc);  \
        px[1] = *(const float4*)(g_comb + (long long)(m0 + lm + 64) * CCC + (K0) + 4 * lc); \
        pw[0] = *(const float4*)(W + (long long)((K0) + lk) * CCC + n0 + 4 * lnq);      \
        pw[1] = *(const float4*)(W + (long long)((K0) + lk + 8) * CCC + n0 + 4 * lnq); }
#define PROJ_STS(BUF) {                                                  \
        float* xp = Xs[BUF]; float* wp = Ws[BUF];                        \
        xp[(4 * lc + 0) * 132 + lm] = px[0].x;                           \
        xp[(4 * lc + 1) * 132 + lm] = px[0].y;                           \
        xp[(4 * lc + 2) * 132 + lm] = px[0].z;                           \
        xp[(4 * lc + 3) * 132 + lm] = px[0].w;                           \
        xp[(4 * lc + 0) * 132 + lm + 64] = px[1].x;                      \
        xp[(4 * lc + 1) * 132 + lm + 64] = px[1].y;                      \
        xp[(4 * lc + 2) * 132 + lm + 64] = px[1].z;                      \
        xp[(4 * lc + 3) * 132 + lm + 64] = px[1].w;                      \
        *(float4*)(wp + lk * 128 + 4 * lnq) = pw[0];                     \
        *(float4*)(wp + (lk + 8) * 128 + 4 * lnq) = pw[1]; }

    PROJ_LDG(0); PROJ_STS(0); PROJ_LDG(16);
    __syncthreads();

    for (int kt = 0; kt < 16; kt++) {
        const float* xp = Xs[kt & 1];
        const float* wp = Ws[kt & 1];
        #pragma unroll
        for (int kk = 0; kk < 16; kk++) {
            float4 aa = *(const float4*)(xp + kk * 132 + ty * 8);
            float4 ab = *(const float4*)(xp + kk * 132 + ty * 8 + 4);
            u64 bp[4];
            #pragma unroll
            for (int c = 0; c < 4; c++)
                bp[c] = *(const u64*)(wp + kk * 128 + tx * 2 + 32 * c);
            float av[8] = {aa.x, aa.y, aa.z, aa.w, ab.x, ab.y, ab.z, ab.w};
            #pragma unroll
            for (int r = 0; r < 8; r++) {
                u64 ap = pack2(av[r], av[r]);
                #pragma unroll
                for (int c = 0; c < 4; c++)
                    acc2[r][c] = fma2(ap, bp[c], acc2[r][c]);
            }
        }
        if (kt < 15) PROJ_STS((kt + 1) & 1);
        if (kt < 14) PROJ_LDG((kt + 2) * 16);
        __syncthreads();
    }
    #pragma unroll
    for (int r = 0; r < 8; r++) {
        int row = m0 + ty * 8 + r;
        #pragma unroll
        for (int c = 0; c < 4; c++) {
            int col = n0 + tx * 2 + 32 * c;
            float lo, hi;
            unpack2(acc2[r][c], lo, hi);
            *(float2*)(out + (long long)row * CCC + col) =
                make_float2(lo + bias[col], hi + bias[col + 1]);
        }
    }
}

// ============================================================
extern "C" void kernel_launch(void* const* d_in, const int* in_sizes, int n_in,
                              void* d_out, int out_size) {
    const float* x     = (const float*)d_in[0];
    const float* Wqkv  = (const float*)d_in[1];
    const float* Wproj = (const float*)d_in[2];
    const float* bproj = (const float*)d_in[3];
    float* out   = (float*)d_out;
    float* out_w = out + (long long)BB * NNN * CCC;

    cudaFuncSetAttribute(attn_global_kernel,
                         cudaFuncAttributeMaxDynamicSharedMemorySize, ATTN_SMEM);

    qkv_gemm_kernel<<<dim3(6, 64), 256>>>(x, Wqkv);
    attn_global_kernel<<<dim3(NNN / 16, BB * HHH), 256, ATTN_SMEM>>>(out_w);
    proj_gemm_kernel<<<dim3(2, 64), 256>>>(Wproj, bproj, out);
}